// round 3
// baseline (speedup 1.0000x reference)
#include <cuda_runtime.h>
#include <math.h>
#include <stdint.h>

#define L      4096
#define DM     768
#define DI     1536
#define DS     16
#define DTR    48
#define NCHUNK 32
#define CHUNK  (L / NCHUNK)

// ---------------- scratch (no allocs allowed) ----------------
__device__ float g_xc_pre[L * DI];          // raw in_proj (xc half)
__device__ float g_xc[L * DI];              // after conv+bias+silu
__device__ float g_dt[L * DI];              // raw dt gemm, then softplus(dt)
__device__ float g_xdbl[L * 64];            // [dt_r(48) | B(16)] per row
__device__ float g_csum[NCHUNK * DI];       // per-chunk dt sums
__device__ float g_csuf[NCHUNK * DI];       // exclusive suffix (sum over later chunks)
__device__ float g_hpart[NCHUNK * DI * DS]; // per-chunk partial h
__device__ float g_h[DI * DS];              // final state
__device__ float g_C[DS];                   // C at last step
__device__ float g_z[DI];                   // z at last step
__device__ float g_y[DI];                   // gated y at last step
__device__ float g_outraw[DM];
__device__ int   g_nexp[DI * DS];
__device__ float g_fexp[DI * DS];
__device__ int   g_fast;

// ---------------- init ----------------
__global__ void k_init() {
    if (threadIdx.x == 0) g_fast = 1;
}

// exponent tables: factor per (d,s) is E^{a} with a = exp(A_log[d,s]), E = exp(-T)
__global__ void k_prep(const float* __restrict__ alog) {
    int i = blockIdx.x * blockDim.x + threadIdx.x;
    if (i >= DI * DS) return;
    int s = i % DS;
    float a = expf(alog[i]);
    int   n = (int)rintf(a);
    float f;
    bool isint = (n >= 0) && (fabsf(a - (float)n) <= 1e-4f * fmaxf(1.f, a));
    if (isint) { f = 0.f; }
    else { n = (int)floorf(a); f = a - (float)n; if (n < 0) { n = 0; f = a; } }
    g_nexp[i] = n;
    g_fexp[i] = f;
    if (!(isint && n == s + 1)) atomicAnd(&g_fast, 0);
}

// ---------------- register-blocked SGEMM body (NT: both K-contiguous) ------
// C[m,n] = sum_k A[m*lda+k] * B[n*ldb+k]
template<int BM, int BN, int BK, int TM, int TN>
__device__ __forceinline__ void sgemm_nt_body(
        int K,
        const float* __restrict__ A, int lda,
        const float* __restrict__ B, int ldb,
        float* __restrict__ C, int ldc) {
    constexpr int THREADS = (BM / TM) * (BN / TN);
    __shared__ float As[BK][BM];
    __shared__ float Bs[BK][BN];
    const int tid = threadIdx.x;
    const int m0 = blockIdx.y * BM;
    const int n0 = blockIdx.x * BN;
    const int tx = tid % (BN / TN);
    const int ty = tid / (BN / TN);

    float acc[TM][TN];
#pragma unroll
    for (int i = 0; i < TM; i++)
#pragma unroll
        for (int j = 0; j < TN; j++) acc[i][j] = 0.f;

    for (int k0 = 0; k0 < K; k0 += BK) {
#pragma unroll
        for (int i = tid; i < BM * (BK / 4); i += THREADS) {
            int r = i / (BK / 4), c = (i % (BK / 4)) * 4;
            float4 v = *reinterpret_cast<const float4*>(A + (size_t)(m0 + r) * lda + k0 + c);
            As[c + 0][r] = v.x; As[c + 1][r] = v.y; As[c + 2][r] = v.z; As[c + 3][r] = v.w;
        }
#pragma unroll
        for (int i = tid; i < BN * (BK / 4); i += THREADS) {
            int r = i / (BK / 4), c = (i % (BK / 4)) * 4;
            float4 v = *reinterpret_cast<const float4*>(B + (size_t)(n0 + r) * ldb + k0 + c);
            Bs[c + 0][r] = v.x; Bs[c + 1][r] = v.y; Bs[c + 2][r] = v.z; Bs[c + 3][r] = v.w;
        }
        __syncthreads();
#pragma unroll
        for (int kk = 0; kk < BK; kk++) {
            float ra[TM], rb[TN];
#pragma unroll
            for (int i = 0; i < TM; i += 4) {
                float4 v = *reinterpret_cast<const float4*>(&As[kk][ty * TM + i]);
                ra[i] = v.x; ra[i + 1] = v.y; ra[i + 2] = v.z; ra[i + 3] = v.w;
            }
#pragma unroll
            for (int j = 0; j < TN; j += 4) {
                float4 v = *reinterpret_cast<const float4*>(&Bs[kk][tx * TN + j]);
                rb[j] = v.x; rb[j + 1] = v.y; rb[j + 2] = v.z; rb[j + 3] = v.w;
            }
#pragma unroll
            for (int i = 0; i < TM; i++)
#pragma unroll
                for (int j = 0; j < TN; j++) acc[i][j] = fmaf(ra[i], rb[j], acc[i][j]);
        }
        __syncthreads();
    }
#pragma unroll
    for (int i = 0; i < TM; i++) {
#pragma unroll
        for (int j = 0; j < TN; j += 4) {
            float4 v;
            v.x = acc[i][j]; v.y = acc[i][j + 1]; v.z = acc[i][j + 2]; v.w = acc[i][j + 3];
            *reinterpret_cast<float4*>(C + (size_t)(m0 + ty * TM + i) * ldc + n0 + tx * TN + j) = v;
        }
    }
}

// GEMM wrappers referencing device globals directly (no cudaGetSymbolAddress)
__global__ void __launch_bounds__(256)
k_gemm1(const float* __restrict__ fe, const float* __restrict__ inw) {
    // xc_pre[4096,1536] = frame_emb[4096,768] @ in_proj_w[0:1536,768]^T
    sgemm_nt_body<128, 128, 16, 8, 8>(DM, fe, DM, inw, DM, g_xc_pre, DI);
}

__global__ void __launch_bounds__(256)
k_gemm2(const float* __restrict__ xpw) {
    // xdbl[4096,64] = xc[4096,1536] @ x_proj_w[0:64,1536]^T
    sgemm_nt_body<64, 64, 16, 4, 4>(DI, g_xc, DI, xpw, DI, g_xdbl, 64);
}

__global__ void __launch_bounds__(256)
k_gemm3(const float* __restrict__ dtw) {
    // dt_raw[4096,1536] = dt_r[4096,48] @ dt_proj_w[1536,48]^T
    sgemm_nt_body<128, 128, 16, 8, 8>(DTR, g_xdbl, 64, dtw, DTR, g_dt, DI);
}

// ---------------- depthwise causal conv(4) + bias + silu ----------------
__global__ void k_conv(const float* __restrict__ w, const float* __restrict__ b) {
    int idx = blockIdx.x * blockDim.x + threadIdx.x;
    if (idx >= L * DI) return;
    int d = idx % DI, l = idx / DI;
    float s = b[d];
#pragma unroll
    for (int k = 0; k < 4; k++) {
        int j = l - 3 + k;
        if (j >= 0) s = fmaf(w[d * 4 + k], g_xc_pre[(size_t)j * DI + d], s);
    }
    g_xc[idx] = s / (1.f + expf(-s));   // silu
}

// ---------------- dt epilogue: dt = softplus(dt_raw + b) in place ---------
__global__ void k_dt_epi(const float* __restrict__ dtb) {
    int idx = blockIdx.x * blockDim.x + threadIdx.x;
    if (idx >= L * DI) return;
    int d = idx % DI;
    float x = g_dt[idx] + dtb[d];
    g_dt[idx] = fmaxf(x, 0.f) + log1pf(expf(-fabsf(x)));   // softplus, stable
}

// ---------------- hierarchical suffix sums of dt ----------------
__global__ void k_chunksum() {
    int i = blockIdx.x * blockDim.x + threadIdx.x;
    if (i >= NCHUNK * DI) return;
    int d = i % DI, c = i / DI;
    float s = 0.f;
    int l0 = c * CHUNK;
#pragma unroll 8
    for (int j = 0; j < CHUNK; j++) s += g_dt[(size_t)(l0 + j) * DI + d];
    g_csum[c * DI + d] = s;
}

__global__ void k_chunksuf() {
    int d = blockIdx.x * blockDim.x + threadIdx.x;
    if (d >= DI) return;
    double t = 0.0;
    for (int c = NCHUNK - 1; c >= 0; --c) {
        g_csuf[c * DI + d] = (float)t;
        t += (double)g_csum[c * DI + d];
    }
}

// ---------------- parallel closed-form scan ----------------
// h[d,s] = sum_l dt[l,d]*xc[l,d] * B[l,s] * E_l^{a_s},  E_l = exp(-T[l,d])
__global__ void k_scan() {
    int d = blockIdx.x * 128 + threadIdx.x;
    int c = blockIdx.y;
    float t = g_csuf[c * DI + d];
    float acc[DS];
#pragma unroll
    for (int s = 0; s < DS; s++) acc[s] = 0.f;
    const int l0 = c * CHUNK;
    const bool fast = (g_fast != 0);

    if (fast) {
        for (int l = l0 + CHUNK - 1; l >= l0; --l) {
            const float* brow = g_xdbl + (size_t)l * 64 + DTR;
            float4 q0 = *reinterpret_cast<const float4*>(brow + 0);
            float4 q1 = *reinterpret_cast<const float4*>(brow + 4);
            float4 q2 = *reinterpret_cast<const float4*>(brow + 8);
            float4 q3 = *reinterpret_cast<const float4*>(brow + 12);
            float bv[16] = {q0.x, q0.y, q0.z, q0.w, q1.x, q1.y, q1.z, q1.w,
                            q2.x, q2.y, q2.z, q2.w, q3.x, q3.y, q3.z, q3.w};
            float dt = g_dt[(size_t)l * DI + d];
            float w  = dt * g_xc[(size_t)l * DI + d];
            float E = expf(-t);
            float p = 1.f;
#pragma unroll
            for (int s = 0; s < DS; s++) { p *= E; acc[s] = fmaf(w * p, bv[s], acc[s]); }
            t += dt;
        }
    } else {
        int nn[DS]; float ff[DS];
#pragma unroll
        for (int s = 0; s < DS; s++) { nn[s] = g_nexp[d * DS + s]; ff[s] = g_fexp[d * DS + s]; }
        for (int l = l0 + CHUNK - 1; l >= l0; --l) {
            const float* brow = g_xdbl + (size_t)l * 64 + DTR;
            float dt = g_dt[(size_t)l * DI + d];
            float w  = dt * g_xc[(size_t)l * DI + d];
            float E = expf(-t);
#pragma unroll
            for (int s = 0; s < DS; s++) {
                float p = 1.f, base = E;
                int m = nn[s];
                while (m) { if (m & 1) p *= base; base *= base; m >>= 1; }
                if (ff[s] != 0.f) p *= expf(-t * ff[s]);
                acc[s] = fmaf(w * p, brow[s], acc[s]);
            }
            t += dt;
        }
    }
#pragma unroll
    for (int s = 0; s < DS; s++)
        g_hpart[(size_t)c * DI * DS + d * DS + s] = acc[s];
}

__global__ void k_hred() {
    int i = blockIdx.x * blockDim.x + threadIdx.x;
    if (i >= DI * DS) return;
    float s = 0.f;
#pragma unroll
    for (int c = 0; c < NCHUNK; c++) s += g_hpart[(size_t)c * DI * DS + i];
    g_h[i] = s;
}

// ---------------- last-step GEMVs ----------------
__global__ void k_zlast(const float* __restrict__ fe, const float* __restrict__ inw) {
    int gw = (blockIdx.x * blockDim.x + threadIdx.x) / 32;
    int lane = threadIdx.x % 32;
    if (gw >= DI) return;
    const float* a = fe + (size_t)(L - 1) * DM;
    const float* w = inw + (size_t)(DI + gw) * DM;
    float s = 0.f;
    for (int m = lane; m < DM; m += 32) s = fmaf(a[m], w[m], s);
#pragma unroll
    for (int o = 16; o; o >>= 1) s += __shfl_xor_sync(0xFFFFFFFFu, s, o);
    if (lane == 0) g_z[gw] = s;
}

__global__ void k_clast(const float* __restrict__ xpw) {
    int s = threadIdx.x / 32;
    int lane = threadIdx.x % 32;
    if (s >= DS) return;
    const float* a = g_xc + (size_t)(L - 1) * DI;
    const float* w = xpw + (size_t)(DTR + DS + s) * DI;
    float acc = 0.f;
    for (int d = lane; d < DI; d += 32) acc = fmaf(a[d], w[d], acc);
#pragma unroll
    for (int o = 16; o; o >>= 1) acc += __shfl_xor_sync(0xFFFFFFFFu, acc, o);
    if (lane == 0) g_C[s] = acc;
}

__global__ void k_y(const float* __restrict__ Dp) {
    int d = blockIdx.x * blockDim.x + threadIdx.x;
    if (d >= DI) return;
    float s = 0.f;
#pragma unroll
    for (int j = 0; j < DS; j++) s = fmaf(g_h[d * DS + j], g_C[j], s);
    float y = s + g_xc[(size_t)(L - 1) * DI + d] * Dp[d];
    float z = g_z[d];
    y *= z / (1.f + expf(-z));
    g_y[d] = y;
}

__global__ void k_out1(const float* __restrict__ outw) {
    int e = blockIdx.x;
    const float* w = outw + (size_t)e * DI;
    float s = 0.f;
    for (int d = threadIdx.x; d < DI; d += 256) s = fmaf(g_y[d], w[d], s);
    __shared__ float red[256];
    red[threadIdx.x] = s;
    __syncthreads();
    for (int o = 128; o >= 1; o >>= 1) {
        if (threadIdx.x < o) red[threadIdx.x] += red[threadIdx.x + o];
        __syncthreads();
    }
    if (threadIdx.x == 0) g_outraw[e] = red[0];
}

__global__ void k_out2(float* __restrict__ out) {
    int t = threadIdx.x;
    float v = g_outraw[t];
    __shared__ float red[768];
    red[t] = v * v;
    __syncthreads();
    if (t < 256) red[t] += red[t + 256] + red[t + 512];
    __syncthreads();
    for (int o = 128; o >= 1; o >>= 1) {
        if (t < o) red[t] += red[t + o];
        __syncthreads();
    }
    float denom = fmaxf(sqrtf(red[0]), 1e-12f);
    out[t] = v / denom;
}

// ---------------- launch ----------------
extern "C" void kernel_launch(void* const* d_in, const int* in_sizes, int n_in,
                              void* d_out, int out_size) {
    const float* fe    = (const float*)d_in[0];
    const float* inw   = (const float*)d_in[1];
    const float* convw = (const float*)d_in[2];
    const float* convb = (const float*)d_in[3];
    const float* xpw   = (const float*)d_in[4];
    const float* dtw   = (const float*)d_in[5];
    const float* dtb   = (const float*)d_in[6];
    const float* alog  = (const float*)d_in[7];
    const float* Dp    = (const float*)d_in[8];
    const float* outw  = (const float*)d_in[9];
    float* out = (float*)d_out;

    k_init<<<1, 32>>>();
    k_prep<<<96, 256>>>(alog);

    k_gemm1<<<dim3(DI / 128, L / 128), 256>>>(fe, inw);

    k_conv<<<(L * DI + 255) / 256, 256>>>(convw, convb);

    k_gemm2<<<dim3(1, L / 64), 256>>>(xpw);

    k_gemm3<<<dim3(DI / 128, L / 128), 256>>>(dtw);

    k_dt_epi<<<(L * DI + 255) / 256, 256>>>(dtb);

    k_chunksum<<<(NCHUNK * DI + 255) / 256, 256>>>();
    k_chunksuf<<<(DI + 255) / 256, 256>>>();
    k_scan<<<dim3(DI / 128, NCHUNK), 128>>>();
    k_hred<<<(DI * DS + 255) / 256, 256>>>();

    k_zlast<<<(DI * 32 + 255) / 256, 256>>>(fe, inw);
    k_clast<<<1, 512>>>(xpw);
    k_y<<<(DI + 255) / 256, 256>>>(Dp);
    k_out1<<<DM, 256>>>(outw);
    k_out2<<<1, 768>>>(out);
}

// round 6
// speedup vs baseline: 1.3451x; 1.3451x over previous
#include <cuda_runtime.h>
#include <cuda_bf16.h>
#include <mma.h>
#include <math.h>
#include <stdint.h>

using namespace nvcuda;

#define L      4096
#define DM     768
#define DI     1536
#define DS     16
#define DTR    48
#define NCHUNK 32
#define CHUNK  (L / NCHUNK)
#define KP     (3 * DM)              // 2304: [hi|hi|lo] x [hi|lo|hi]

// ---------------- scratch (no allocs allowed) ----------------
__device__ float g_xc_pre[L * DI];          // raw in_proj (xc half)
__device__ float g_xc[L * DI];              // after conv+bias+silu
__device__ float g_dt[L * DI];              // softplus(dt) (epilogue-fused)
__device__ float g_xdbl[L * 64];            // [dt_r(48) | B(16)] per row
__device__ float g_csum[NCHUNK * DI];
__device__ float g_csuf[NCHUNK * DI];
__device__ float g_hpart[NCHUNK * DI * DS];
__device__ float g_h[DI * DS];
__device__ float g_C[DS];
__device__ float g_z[DI];
__device__ float g_y[DI];
__device__ float g_outraw[DM];
__device__ int   g_nexp[DI * DS];
__device__ float g_fexp[DI * DS];
__device__ int   g_fast;
// split-bf16 K-concatenated operands for WMMA GEMM1
__device__ __nv_bfloat16 g_feS[L * KP];     // [ah | ah | al]
__device__ __nv_bfloat16 g_wS[DI * KP];     // [bh | bl | bh]

// ---------------- init & prep ----------------
__global__ void k_init() { if (threadIdx.x == 0) g_fast = 1; }

__global__ void k_prep(const float* __restrict__ alog) {
    int i = blockIdx.x * blockDim.x + threadIdx.x;
    if (i >= DI * DS) return;
    int s = i % DS;
    float a = expf(alog[i]);
    int   n = (int)rintf(a);
    float f;
    bool isint = (n >= 0) && (fabsf(a - (float)n) <= 1e-4f * fmaxf(1.f, a));
    if (isint) { f = 0.f; }
    else { n = (int)floorf(a); f = a - (float)n; if (n < 0) { n = 0; f = a; } }
    g_nexp[i] = n;
    g_fexp[i] = f;
    if (!(isint && n == s + 1)) atomicAnd(&g_fast, 0);
}

// ---------------- split conversions (K-concatenated layout) ----------------
__global__ void k_cvt_fe(const float* __restrict__ fe) {
    int i = blockIdx.x * blockDim.x + threadIdx.x;
    if (i >= L * DM) return;
    float x = fe[i];
    __nv_bfloat16 h = __float2bfloat16(x);
    __nv_bfloat16 lo = __float2bfloat16(x - __bfloat162float(h));
    int row = i / DM, col = i % DM;
    size_t base = (size_t)row * KP;
    g_feS[base + col]            = h;
    g_feS[base + DM + col]       = h;
    g_feS[base + 2 * DM + col]   = lo;
}
__global__ void k_cvt_w(const float* __restrict__ inw) {
    int i = blockIdx.x * blockDim.x + threadIdx.x;
    if (i >= DI * DM) return;
    float x = inw[i];                         // rows 0..DI-1 (the xc half)
    __nv_bfloat16 h = __float2bfloat16(x);
    __nv_bfloat16 lo = __float2bfloat16(x - __bfloat162float(h));
    int row = i / DM, col = i % DM;
    size_t base = (size_t)row * KP;
    g_wS[base + col]            = h;
    g_wS[base + DM + col]       = lo;
    g_wS[base + 2 * DM + col]   = h;
}

// ---------------- WMMA GEMM1: xc_pre[4096,1536] = feS @ wS^T over K'=2304 --
#define G1_BK 32
#define G1_PAD 8
#define G1_LD (G1_BK + G1_PAD)      // 40

__global__ void __launch_bounds__(256)
k_gemm1_wmma() {
    __shared__ alignas(16) __nv_bfloat16 sA[128][G1_LD];
    __shared__ alignas(16) __nv_bfloat16 sB[128][G1_LD];
    const int tid = threadIdx.x;
    const int wid = tid >> 5;
    const int wm = wid & 3;          // 4 m-tiles of 32
    const int wn = wid >> 2;         // 2 n-tiles of 64
    const int m0 = blockIdx.y * 128;
    const int n0 = blockIdx.x * 128;

    wmma::fragment<wmma::accumulator, 16, 16, 16, float> acc[2][4];
#pragma unroll
    for (int i = 0; i < 2; i++)
#pragma unroll
        for (int j = 0; j < 4; j++) wmma::fill_fragment(acc[i][j], 0.f);

    for (int k0 = 0; k0 < KP; k0 += G1_BK) {
        // stage A,B tiles: 128 rows x 32 bf16 = 64B/row -> 4 x 16B chunks
#pragma unroll
        for (int j = tid; j < 512; j += 256) {
            int r = j >> 2, c = (j & 3) << 3;     // c in elements (8 bf16 = 16B)
            *reinterpret_cast<uint4*>(&sA[r][c]) =
                *reinterpret_cast<const uint4*>(&g_feS[(size_t)(m0 + r) * KP + k0 + c]);
            *reinterpret_cast<uint4*>(&sB[r][c]) =
                *reinterpret_cast<const uint4*>(&g_wS[(size_t)(n0 + r) * KP + k0 + c]);
        }
        __syncthreads();
#pragma unroll
        for (int kk = 0; kk < G1_BK; kk += 16) {
            wmma::fragment<wmma::matrix_a, 16, 16, 16, __nv_bfloat16, wmma::row_major> fa[2];
            wmma::fragment<wmma::matrix_b, 16, 16, 16, __nv_bfloat16, wmma::col_major> fb[4];
#pragma unroll
            for (int i = 0; i < 2; i++)
                wmma::load_matrix_sync(fa[i], &sA[wm * 32 + i * 16][kk], G1_LD);
#pragma unroll
            for (int j = 0; j < 4; j++)
                wmma::load_matrix_sync(fb[j], &sB[wn * 64 + j * 16][kk], G1_LD);
#pragma unroll
            for (int i = 0; i < 2; i++)
#pragma unroll
                for (int j = 0; j < 4; j++)
                    wmma::mma_sync(acc[i][j], fa[i], fb[j], acc[i][j]);
        }
        __syncthreads();
    }
#pragma unroll
    for (int i = 0; i < 2; i++)
#pragma unroll
        for (int j = 0; j < 4; j++)
            wmma::store_matrix_sync(
                &g_xc_pre[(size_t)(m0 + wm * 32 + i * 16) * DI + n0 + wn * 64 + j * 16],
                acc[i][j], DI, wmma::mem_row_major);
}

// ---------------- SIMT SGEMM body (NT) for small GEMMs ----------------
template<int BM, int BN, int BK, int TM, int TN, bool SOFTPLUS>
__device__ __forceinline__ void sgemm_nt_body(
        int K,
        const float* __restrict__ A, int lda,
        const float* __restrict__ B, int ldb,
        float* __restrict__ C, int ldc,
        const float* __restrict__ bias) {
    constexpr int THREADS = (BM / TM) * (BN / TN);
    __shared__ float As[BK][BM];
    __shared__ float Bs[BK][BN];
    const int tid = threadIdx.x;
    const int m0 = blockIdx.y * BM;
    const int n0 = blockIdx.x * BN;
    const int tx = tid % (BN / TN);
    const int ty = tid / (BN / TN);

    float acc[TM][TN];
#pragma unroll
    for (int i = 0; i < TM; i++)
#pragma unroll
        for (int j = 0; j < TN; j++) acc[i][j] = 0.f;

    for (int k0 = 0; k0 < K; k0 += BK) {
#pragma unroll
        for (int i = tid; i < BM * (BK / 4); i += THREADS) {
            int r = i / (BK / 4), c = (i % (BK / 4)) * 4;
            float4 v = *reinterpret_cast<const float4*>(A + (size_t)(m0 + r) * lda + k0 + c);
            As[c + 0][r] = v.x; As[c + 1][r] = v.y; As[c + 2][r] = v.z; As[c + 3][r] = v.w;
        }
#pragma unroll
        for (int i = tid; i < BN * (BK / 4); i += THREADS) {
            int r = i / (BK / 4), c = (i % (BK / 4)) * 4;
            float4 v = *reinterpret_cast<const float4*>(B + (size_t)(n0 + r) * ldb + k0 + c);
            Bs[c + 0][r] = v.x; Bs[c + 1][r] = v.y; Bs[c + 2][r] = v.z; Bs[c + 3][r] = v.w;
        }
        __syncthreads();
#pragma unroll
        for (int kk = 0; kk < BK; kk++) {
            float ra[TM], rb[TN];
#pragma unroll
            for (int i = 0; i < TM; i += 4) {
                float4 v = *reinterpret_cast<const float4*>(&As[kk][ty * TM + i]);
                ra[i] = v.x; ra[i + 1] = v.y; ra[i + 2] = v.z; ra[i + 3] = v.w;
            }
#pragma unroll
            for (int j = 0; j < TN; j += 4) {
                float4 v = *reinterpret_cast<const float4*>(&Bs[kk][tx * TN + j]);
                rb[j] = v.x; rb[j + 1] = v.y; rb[j + 2] = v.z; rb[j + 3] = v.w;
            }
#pragma unroll
            for (int i = 0; i < TM; i++)
#pragma unroll
                for (int j = 0; j < TN; j++) acc[i][j] = fmaf(ra[i], rb[j], acc[i][j]);
        }
        __syncthreads();
    }
#pragma unroll
    for (int i = 0; i < TM; i++) {
#pragma unroll
        for (int j = 0; j < TN; j += 4) {
            float vv[4];
#pragma unroll
            for (int t = 0; t < 4; t++) vv[t] = acc[i][j + t];
            if (SOFTPLUS) {
                int col = n0 + tx * TN + j;
#pragma unroll
                for (int t = 0; t < 4; t++) {
                    float x = vv[t] + bias[col + t];
                    vv[t] = fmaxf(x, 0.f) + log1pf(expf(-fabsf(x)));
                }
            }
            float4 v = make_float4(vv[0], vv[1], vv[2], vv[3]);
            *reinterpret_cast<float4*>(C + (size_t)(m0 + ty * TM + i) * ldc + n0 + tx * TN + j) = v;
        }
    }
}

__global__ void __launch_bounds__(256)
k_gemm2(const float* __restrict__ xpw) {
    // xdbl[4096,64] = xc[4096,1536] @ x_proj_w[0:64,1536]^T
    sgemm_nt_body<64, 64, 16, 4, 4, false>(DI, g_xc, DI, xpw, DI, g_xdbl, 64, nullptr);
}

__global__ void __launch_bounds__(256)
k_gemm3(const float* __restrict__ dtw, const float* __restrict__ dtb) {
    // dt[4096,1536] = softplus(dt_r[4096,48] @ dt_proj_w^T + dtb)
    sgemm_nt_body<128, 128, 16, 8, 8, true>(DTR, g_xdbl, 64, dtw, DTR, g_dt, DI, dtb);
}

// ---------------- depthwise causal conv(4) + bias + silu (4 l per thread) --
__global__ void k_conv(const float* __restrict__ w, const float* __restrict__ b) {
    int idx = blockIdx.x * blockDim.x + threadIdx.x;
    if (idx >= DI * (L / 4)) return;
    int d = idx % DI, g = idx / DI;
    int l0 = g * 4;
    float w0 = w[d * 4 + 0], w1 = w[d * 4 + 1], w2 = w[d * 4 + 2], w3 = w[d * 4 + 3];
    float bb = b[d];
    float x[7];
#pragma unroll
    for (int t = 0; t < 7; t++) {
        int l = l0 - 3 + t;
        x[t] = (l >= 0) ? g_xc_pre[(size_t)l * DI + d] : 0.f;
    }
#pragma unroll
    for (int t = 0; t < 4; t++) {
        float s = bb;
        s = fmaf(w0, x[t], s); s = fmaf(w1, x[t + 1], s);
        s = fmaf(w2, x[t + 2], s); s = fmaf(w3, x[t + 3], s);
        g_xc[(size_t)(l0 + t) * DI + d] = s / (1.f + expf(-s));
    }
}

// ---------------- hierarchical suffix sums of dt ----------------
__global__ void k_chunksum() {
    int i = blockIdx.x * blockDim.x + threadIdx.x;
    if (i >= NCHUNK * DI) return;
    int d = i % DI, c = i / DI;
    float s = 0.f;
    int l0 = c * CHUNK;
#pragma unroll 8
    for (int j = 0; j < CHUNK; j++) s += g_dt[(size_t)(l0 + j) * DI + d];
    g_csum[c * DI + d] = s;
}

__global__ void k_chunksuf() {
    int d = blockIdx.x * blockDim.x + threadIdx.x;
    if (d >= DI) return;
    double t = 0.0;
    for (int c = NCHUNK - 1; c >= 0; --c) {
        g_csuf[c * DI + d] = (float)t;
        t += (double)g_csum[c * DI + d];
    }
}

// ---------------- parallel closed-form scan ----------------
__global__ void k_scan() {
    int d = blockIdx.x * 128 + threadIdx.x;
    int c = blockIdx.y;
    float t = g_csuf[c * DI + d];
    float acc[DS];
#pragma unroll
    for (int s = 0; s < DS; s++) acc[s] = 0.f;
    const int l0 = c * CHUNK;
    const bool fast = (g_fast != 0);

    if (fast) {
        for (int l = l0 + CHUNK - 1; l >= l0; --l) {
            const float* brow = g_xdbl + (size_t)l * 64 + DTR;
            float4 q0 = *reinterpret_cast<const float4*>(brow + 0);
            float4 q1 = *reinterpret_cast<const float4*>(brow + 4);
            float4 q2 = *reinterpret_cast<const float4*>(brow + 8);
            float4 q3 = *reinterpret_cast<const float4*>(brow + 12);
            float bv[16] = {q0.x, q0.y, q0.z, q0.w, q1.x, q1.y, q1.z, q1.w,
                            q2.x, q2.y, q2.z, q2.w, q3.x, q3.y, q3.z, q3.w};
            float dt = g_dt[(size_t)l * DI + d];
            float w  = dt * g_xc[(size_t)l * DI + d];
            float E = expf(-t);
            float p = 1.f;
#pragma unroll
            for (int s = 0; s < DS; s++) { p *= E; acc[s] = fmaf(w * p, bv[s], acc[s]); }
            t += dt;
        }
    } else {
        int nn[DS]; float ff[DS];
#pragma unroll
        for (int s = 0; s < DS; s++) { nn[s] = g_nexp[d * DS + s]; ff[s] = g_fexp[d * DS + s]; }
        for (int l = l0 + CHUNK - 1; l >= l0; --l) {
            const float* brow = g_xdbl + (size_t)l * 64 + DTR;
            float dt = g_dt[(size_t)l * DI + d];
            float w  = dt * g_xc[(size_t)l * DI + d];
            float E = expf(-t);
#pragma unroll
            for (int s = 0; s < DS; s++) {
                float p = 1.f, base = E;
                int m = nn[s];
                while (m) { if (m & 1) p *= base; base *= base; m >>= 1; }
                if (ff[s] != 0.f) p *= expf(-t * ff[s]);
                acc[s] = fmaf(w * p, brow[s], acc[s]);
            }
            t += dt;
        }
    }
#pragma unroll
    for (int s = 0; s < DS; s++)
        g_hpart[(size_t)c * DI * DS + d * DS + s] = acc[s];
}

__global__ void k_hred() {
    int i = blockIdx.x * blockDim.x + threadIdx.x;
    if (i >= DI * DS) return;
    float s = 0.f;
#pragma unroll
    for (int c = 0; c < NCHUNK; c++) s += g_hpart[(size_t)c * DI * DS + i];
    g_h[i] = s;
}

// ---------------- last-step GEMVs ----------------
__global__ void k_zlast(const float* __restrict__ fe, const float* __restrict__ inw) {
    int gw = (blockIdx.x * blockDim.x + threadIdx.x) / 32;
    int lane = threadIdx.x % 32;
    if (gw >= DI) return;
    const float* a = fe + (size_t)(L - 1) * DM;
    const float* w = inw + (size_t)(DI + gw) * DM;
    float s = 0.f;
    for (int m = lane; m < DM; m += 32) s = fmaf(a[m], w[m], s);
#pragma unroll
    for (int o = 16; o; o >>= 1) s += __shfl_xor_sync(0xFFFFFFFFu, s, o);
    if (lane == 0) g_z[gw] = s;
}

__global__ void k_clast(const float* __restrict__ xpw) {
    int s = threadIdx.x / 32;
    int lane = threadIdx.x % 32;
    if (s >= DS) return;
    const float* a = g_xc + (size_t)(L - 1) * DI;
    const float* w = xpw + (size_t)(DTR + DS + s) * DI;
    float acc = 0.f;
    for (int d = lane; d < DI; d += 32) acc = fmaf(a[d], w[d], acc);
#pragma unroll
    for (int o = 16; o; o >>= 1) acc += __shfl_xor_sync(0xFFFFFFFFu, acc, o);
    if (lane == 0) g_C[s] = acc;
}

__global__ void k_y(const float* __restrict__ Dp) {
    int d = blockIdx.x * blockDim.x + threadIdx.x;
    if (d >= DI) return;
    float s = 0.f;
#pragma unroll
    for (int j = 0; j < DS; j++) s = fmaf(g_h[d * DS + j], g_C[j], s);
    float y = s + g_xc[(size_t)(L - 1) * DI + d] * Dp[d];
    float z = g_z[d];
    y *= z / (1.f + expf(-z));
    g_y[d] = y;
}

__global__ void k_out1(const float* __restrict__ outw) {
    int e = blockIdx.x;
    const float* w = outw + (size_t)e * DI;
    float s = 0.f;
    for (int d = threadIdx.x; d < DI; d += 256) s = fmaf(g_y[d], w[d], s);
    __shared__ float red[256];
    red[threadIdx.x] = s;
    __syncthreads();
    for (int o = 128; o >= 1; o >>= 1) {
        if (threadIdx.x < o) red[threadIdx.x] += red[threadIdx.x + o];
        __syncthreads();
    }
    if (threadIdx.x == 0) g_outraw[e] = red[0];
}

__global__ void k_out2(float* __restrict__ out) {
    int t = threadIdx.x;
    float v = g_outraw[t];
    __shared__ float red[768];
    red[t] = v * v;
    __syncthreads();
    if (t < 256) red[t] += red[t + 256] + red[t + 512];
    __syncthreads();
    for (int o = 128; o >= 1; o >>= 1) {
        if (t < o) red[t] += red[t + o];
        __syncthreads();
    }
    float denom = fmaxf(sqrtf(red[0]), 1e-12f);
    out[t] = v / denom;
}

// ---------------- launch ----------------
extern "C" void kernel_launch(void* const* d_in, const int* in_sizes, int n_in,
                              void* d_out, int out_size) {
    const float* fe    = (const float*)d_in[0];
    const float* inw   = (const float*)d_in[1];
    const float* convw = (const float*)d_in[2];
    const float* convb = (const float*)d_in[3];
    const float* xpw   = (const float*)d_in[4];
    const float* dtw   = (const float*)d_in[5];
    const float* dtb   = (const float*)d_in[6];
    const float* alog  = (const float*)d_in[7];
    const float* Dp    = (const float*)d_in[8];
    const float* outw  = (const float*)d_in[9];
    float* out = (float*)d_out;

    k_init<<<1, 32>>>();
    k_prep<<<96, 256>>>(alog);
    k_cvt_fe<<<(L * DM + 255) / 256, 256>>>(fe);
    k_cvt_w<<<(DI * DM + 255) / 256, 256>>>(inw);

    k_gemm1_wmma<<<dim3(DI / 128, L / 128), 256>>>();

    k_conv<<<(DI * (L / 4) + 255) / 256, 256>>>(convw, convb);

    k_gemm2<<<dim3(1, L / 64), 256>>>(xpw);
    k_gemm3<<<dim3(DI / 128, L / 128), 256>>>(dtw, dtb);

    k_chunksum<<<(NCHUNK * DI + 255) / 256, 256>>>();
    k_chunksuf<<<(DI + 255) / 256, 256>>>();
    k_scan<<<dim3(DI / 128, NCHUNK), 128>>>();
    k_hred<<<(DI * DS + 255) / 256, 256>>>();

    k_zlast<<<(DI * 32 + 255) / 256, 256>>>(fe, inw);
    k_clast<<<1, 512>>>(xpw);
    k_y<<<(DI + 255) / 256, 256>>>(Dp);
    k_out1<<<DM, 256>>>(outw);
    k_out2<<<1, 768>>>(out);
}

// round 7
// speedup vs baseline: 1.6607x; 1.2347x over previous
#include <cuda_runtime.h>
#include <cuda_bf16.h>
#include <mma.h>
#include <math.h>
#include <stdint.h>

using namespace nvcuda;

#define L      4096
#define DM     768
#define DI     1536
#define DS     16
#define DTR    48
#define NCHUNK 32
#define CHUNK  (L / NCHUNK)
#define KP     (3 * DM)              // 2304: [hi|hi|lo] x [hi|lo|hi]
#define KS2    6                     // gemm2 K-splits
#define KC2    (DI / KS2)            // 256

// ---------------- scratch (no allocs allowed) ----------------
__device__ float g_xc_pre[L * DI];
__device__ float g_xc[L * DI];
__device__ float g_dt[L * DI];
__device__ float g_xdbl[L * 64];
__device__ float g_xdbl_part[KS2][L * 64];
__device__ float g_csum[NCHUNK * DI];
__device__ float g_csuf[NCHUNK * DI];
__device__ float g_hpart[NCHUNK * DI * DS];
__device__ float g_h[DI * DS];
__device__ float g_C[DS];
__device__ float g_z[DI];
__device__ float g_y[DI];
__device__ float g_outraw[DM];
__device__ int   g_nexp[DI * DS];
__device__ float g_fexp[DI * DS];
__device__ int   g_fast;
__device__ __nv_bfloat16 g_feS[L * KP];     // [ah | ah | al]
__device__ __nv_bfloat16 g_wS[DI * KP];     // [bh | bl | bh]

__device__ __forceinline__ uint32_t smem_u32(const void* p) {
    uint32_t a;
    asm("{ .reg .u64 t; cvta.to.shared.u64 t, %1; cvt.u32.u64 %0, t; }" : "=r"(a) : "l"(p));
    return a;
}

// ---------------- init & prep ----------------
__global__ void k_init() { if (threadIdx.x == 0) g_fast = 1; }

__global__ void k_prep(const float* __restrict__ alog) {
    int i = blockIdx.x * blockDim.x + threadIdx.x;
    if (i >= DI * DS) return;
    int s = i % DS;
    float a = expf(alog[i]);
    int   n = (int)rintf(a);
    float f;
    bool isint = (n >= 0) && (fabsf(a - (float)n) <= 1e-4f * fmaxf(1.f, a));
    if (isint) { f = 0.f; }
    else { n = (int)floorf(a); f = a - (float)n; if (n < 0) { n = 0; f = a; } }
    g_nexp[i] = n;
    g_fexp[i] = f;
    if (!(isint && n == s + 1)) atomicAnd(&g_fast, 0);
}

// ---------------- split conversions (K-concatenated layout) ----------------
__global__ void k_cvt_fe(const float* __restrict__ fe) {
    int i = blockIdx.x * blockDim.x + threadIdx.x;
    if (i >= L * DM) return;
    float x = fe[i];
    __nv_bfloat16 h = __float2bfloat16(x);
    __nv_bfloat16 lo = __float2bfloat16(x - __bfloat162float(h));
    int row = i / DM, col = i % DM;
    size_t base = (size_t)row * KP;
    g_feS[base + col]          = h;
    g_feS[base + DM + col]     = h;
    g_feS[base + 2 * DM + col] = lo;
}
__global__ void k_cvt_w(const float* __restrict__ inw) {
    int i = blockIdx.x * blockDim.x + threadIdx.x;
    if (i >= DI * DM) return;
    float x = inw[i];
    __nv_bfloat16 h = __float2bfloat16(x);
    __nv_bfloat16 lo = __float2bfloat16(x - __bfloat162float(h));
    int row = i / DM, col = i % DM;
    size_t base = (size_t)row * KP;
    g_wS[base + col]          = h;
    g_wS[base + DM + col]     = lo;
    g_wS[base + 2 * DM + col] = h;
}

// ---------------- WMMA GEMM1 with 2-stage cp.async pipeline ----------------
#define G1_BK 32
#define G1_LD 40                     // 32 + 8 pad (80B row stride, 16B-aligned)
#define G1_NT (KP / G1_BK)           // 72

__global__ void __launch_bounds__(256)
k_gemm1_wmma() {
    __shared__ alignas(16) __nv_bfloat16 sA[2][128][G1_LD];
    __shared__ alignas(16) __nv_bfloat16 sB[2][128][G1_LD];
    const int tid = threadIdx.x;
    const int wid = tid >> 5;
    const int wm = wid & 3;
    const int wn = wid >> 2;
    const int m0 = blockIdx.y * 128;
    const int n0 = blockIdx.x * 128;

    wmma::fragment<wmma::accumulator, 16, 16, 16, float> acc[2][4];
#pragma unroll
    for (int i = 0; i < 2; i++)
#pragma unroll
        for (int j = 0; j < 4; j++) wmma::fill_fragment(acc[i][j], 0.f);

    const int r0 = tid >> 2;                 // row for this thread's 2 chunks (stride 64)
    const int c0 = (tid & 3) << 3;           // col in elements

    // stage issue: 128 rows x 32 cols bf16 = 512 x 16B per array; 2 per thread
#define G1_ISSUE(st, k0)                                                              \
    do {                                                                              \
        _Pragma("unroll")                                                             \
        for (int h = 0; h < 2; h++) {                                                 \
            int r = r0 + h * 64;                                                      \
            uint32_t sa = smem_u32(&sA[st][r][c0]);                                   \
            uint32_t sb = smem_u32(&sB[st][r][c0]);                                   \
            const void* ga = &g_feS[(size_t)(m0 + r) * KP + (k0) + c0];               \
            const void* gb = &g_wS[(size_t)(n0 + r) * KP + (k0) + c0];                \
            asm volatile("cp.async.cg.shared.global [%0], [%1], 16;" :: "r"(sa), "l"(ga)); \
            asm volatile("cp.async.cg.shared.global [%0], [%1], 16;" :: "r"(sb), "l"(gb)); \
        }                                                                             \
        asm volatile("cp.async.commit_group;");                                       \
    } while (0)

    G1_ISSUE(0, 0);
    for (int t = 0; t < G1_NT; t++) {
        if (t + 1 < G1_NT) {
            G1_ISSUE((t + 1) & 1, (t + 1) * G1_BK);
            asm volatile("cp.async.wait_group 1;");
        } else {
            asm volatile("cp.async.wait_group 0;");
        }
        __syncthreads();
        const int st = t & 1;
#pragma unroll
        for (int kk = 0; kk < G1_BK; kk += 16) {
            wmma::fragment<wmma::matrix_a, 16, 16, 16, __nv_bfloat16, wmma::row_major> fa[2];
            wmma::fragment<wmma::matrix_b, 16, 16, 16, __nv_bfloat16, wmma::col_major> fb[4];
#pragma unroll
            for (int i = 0; i < 2; i++)
                wmma::load_matrix_sync(fa[i], &sA[st][wm * 32 + i * 16][kk], G1_LD);
#pragma unroll
            for (int j = 0; j < 4; j++)
                wmma::load_matrix_sync(fb[j], &sB[st][wn * 64 + j * 16][kk], G1_LD);
#pragma unroll
            for (int i = 0; i < 2; i++)
#pragma unroll
                for (int j = 0; j < 4; j++)
                    wmma::mma_sync(acc[i][j], fa[i], fb[j], acc[i][j]);
        }
        __syncthreads();
    }
#pragma unroll
    for (int i = 0; i < 2; i++)
#pragma unroll
        for (int j = 0; j < 4; j++)
            wmma::store_matrix_sync(
                &g_xc_pre[(size_t)(m0 + wm * 32 + i * 16) * DI + n0 + wn * 64 + j * 16],
                acc[i][j], DI, wmma::mem_row_major);
}

// ---------------- SIMT SGEMM body (NT) ----------------
template<int BM, int BN, int BK, int TM, int TN, bool SOFTPLUS>
__device__ __forceinline__ void sgemm_nt_body(
        int kbeg, int kend,
        const float* __restrict__ A, int lda,
        const float* __restrict__ B, int ldb,
        float* __restrict__ C, int ldc,
        const float* __restrict__ bias,
        int m0, int n0) {
    constexpr int THREADS = (BM / TM) * (BN / TN);
    __shared__ float As[BK][BM];
    __shared__ float Bs[BK][BN];
    const int tid = threadIdx.x;
    const int tx = tid % (BN / TN);
    const int ty = tid / (BN / TN);

    float acc[TM][TN];
#pragma unroll
    for (int i = 0; i < TM; i++)
#pragma unroll
        for (int j = 0; j < TN; j++) acc[i][j] = 0.f;

    for (int k0 = kbeg; k0 < kend; k0 += BK) {
#pragma unroll
        for (int i = tid; i < BM * (BK / 4); i += THREADS) {
            int r = i / (BK / 4), c = (i % (BK / 4)) * 4;
            float4 v = *reinterpret_cast<const float4*>(A + (size_t)(m0 + r) * lda + k0 + c);
            As[c + 0][r] = v.x; As[c + 1][r] = v.y; As[c + 2][r] = v.z; As[c + 3][r] = v.w;
        }
#pragma unroll
        for (int i = tid; i < BN * (BK / 4); i += THREADS) {
            int r = i / (BK / 4), c = (i % (BK / 4)) * 4;
            float4 v = *reinterpret_cast<const float4*>(B + (size_t)(n0 + r) * ldb + k0 + c);
            Bs[c + 0][r] = v.x; Bs[c + 1][r] = v.y; Bs[c + 2][r] = v.z; Bs[c + 3][r] = v.w;
        }
        __syncthreads();
#pragma unroll
        for (int kk = 0; kk < BK; kk++) {
            float ra[TM], rb[TN];
#pragma unroll
            for (int i = 0; i < TM; i += 4) {
                float4 v = *reinterpret_cast<const float4*>(&As[kk][ty * TM + i]);
                ra[i] = v.x; ra[i + 1] = v.y; ra[i + 2] = v.z; ra[i + 3] = v.w;
            }
#pragma unroll
            for (int j = 0; j < TN; j += 4) {
                float4 v = *reinterpret_cast<const float4*>(&Bs[kk][tx * TN + j]);
                rb[j] = v.x; rb[j + 1] = v.y; rb[j + 2] = v.z; rb[j + 3] = v.w;
            }
#pragma unroll
            for (int i = 0; i < TM; i++)
#pragma unroll
                for (int j = 0; j < TN; j++) acc[i][j] = fmaf(ra[i], rb[j], acc[i][j]);
        }
        __syncthreads();
    }
#pragma unroll
    for (int i = 0; i < TM; i++) {
#pragma unroll
        for (int j = 0; j < TN; j += 4) {
            float vv[4];
#pragma unroll
            for (int t = 0; t < 4; t++) vv[t] = acc[i][j + t];
            if (SOFTPLUS) {
                int col = n0 + tx * TN + j;
#pragma unroll
                for (int t = 0; t < 4; t++) {
                    float x = vv[t] + bias[col + t];
                    vv[t] = fmaxf(x, 0.f) + log1pf(__expf(-fabsf(x)));
                }
            }
            float4 v = make_float4(vv[0], vv[1], vv[2], vv[3]);
            *reinterpret_cast<float4*>(C + (size_t)(m0 + ty * TM + i) * ldc + n0 + tx * TN + j) = v;
        }
    }
}

// gemm2 split-K: partial xdbl per K-chunk
__global__ void __launch_bounds__(256)
k_gemm2(const float* __restrict__ xpw) {
    int ck = blockIdx.x;                 // 0..KS2-1
    sgemm_nt_body<64, 64, 16, 4, 4, false>(
        ck * KC2, (ck + 1) * KC2,
        g_xc, DI, xpw, DI, g_xdbl_part[ck], 64, nullptr,
        blockIdx.y * 64, 0);
}

__global__ void k_xdblred() {
    int i = blockIdx.x * blockDim.x + threadIdx.x;
    if (i >= L * 64) return;
    float s = 0.f;
#pragma unroll
    for (int c = 0; c < KS2; c++) s += g_xdbl_part[c][i];
    g_xdbl[i] = s;
}

__global__ void __launch_bounds__(256)
k_gemm3(const float* __restrict__ dtw, const float* __restrict__ dtb) {
    sgemm_nt_body<128, 128, 16, 8, 8, true>(
        0, DTR, g_xdbl, 64, dtw, DTR, g_dt, DI, dtb,
        blockIdx.y * 128, blockIdx.x * 128);
}

// ---------------- depthwise causal conv(4) + bias + silu ----------------
__global__ void k_conv(const float* __restrict__ w, const float* __restrict__ b) {
    int idx = blockIdx.x * blockDim.x + threadIdx.x;
    if (idx >= DI * (L / 4)) return;
    int d = idx % DI, g = idx / DI;
    int l0 = g * 4;
    float w0 = w[d * 4 + 0], w1 = w[d * 4 + 1], w2 = w[d * 4 + 2], w3 = w[d * 4 + 3];
    float bb = b[d];
    float x[7];
#pragma unroll
    for (int t = 0; t < 7; t++) {
        int l = l0 - 3 + t;
        x[t] = (l >= 0) ? g_xc_pre[(size_t)l * DI + d] : 0.f;
    }
#pragma unroll
    for (int t = 0; t < 4; t++) {
        float s = bb;
        s = fmaf(w0, x[t], s); s = fmaf(w1, x[t + 1], s);
        s = fmaf(w2, x[t + 2], s); s = fmaf(w3, x[t + 3], s);
        g_xc[(size_t)(l0 + t) * DI + d] = s / (1.f + __expf(-s));
    }
}

// ---------------- hierarchical suffix sums of dt ----------------
__global__ void k_chunksum() {
    int i = blockIdx.x * blockDim.x + threadIdx.x;
    if (i >= NCHUNK * DI) return;
    int d = i % DI, c = i / DI;
    float s = 0.f;
    int l0 = c * CHUNK;
#pragma unroll 8
    for (int j = 0; j < CHUNK; j++) s += g_dt[(size_t)(l0 + j) * DI + d];
    g_csum[c * DI + d] = s;
}

__global__ void k_chunksuf() {
    int d = blockIdx.x * blockDim.x + threadIdx.x;
    if (d >= DI) return;
    double t = 0.0;
    for (int c = NCHUNK - 1; c >= 0; --c) {
        g_csuf[c * DI + d] = (float)t;
        t += (double)g_csum[c * DI + d];
    }
}

// ---------------- parallel closed-form scan ----------------
__global__ void k_scan() {
    int d = blockIdx.x * 128 + threadIdx.x;
    int c = blockIdx.y;
    float t = g_csuf[c * DI + d];
    float acc[DS];
#pragma unroll
    for (int s = 0; s < DS; s++) acc[s] = 0.f;
    const int l0 = c * CHUNK;
    const bool fast = (g_fast != 0);

    if (fast) {
        for (int l = l0 + CHUNK - 1; l >= l0; --l) {
            const float* brow = g_xdbl + (size_t)l * 64 + DTR;
            float4 q0 = *reinterpret_cast<const float4*>(brow + 0);
            float4 q1 = *reinterpret_cast<const float4*>(brow + 4);
            float4 q2 = *reinterpret_cast<const float4*>(brow + 8);
            float4 q3 = *reinterpret_cast<const float4*>(brow + 12);
            float bv[16] = {q0.x, q0.y, q0.z, q0.w, q1.x, q1.y, q1.z, q1.w,
                            q2.x, q2.y, q2.z, q2.w, q3.x, q3.y, q3.z, q3.w};
            float dt = g_dt[(size_t)l * DI + d];
            float w  = dt * g_xc[(size_t)l * DI + d];
            float E = __expf(-t);
            float p = 1.f;
#pragma unroll
            for (int s = 0; s < DS; s++) { p *= E; acc[s] = fmaf(w * p, bv[s], acc[s]); }
            t += dt;
        }
    } else {
        int nn[DS]; float ff[DS];
#pragma unroll
        for (int s = 0; s < DS; s++) { nn[s] = g_nexp[d * DS + s]; ff[s] = g_fexp[d * DS + s]; }
        for (int l = l0 + CHUNK - 1; l >= l0; --l) {
            const float* brow = g_xdbl + (size_t)l * 64 + DTR;
            float dt = g_dt[(size_t)l * DI + d];
            float w  = dt * g_xc[(size_t)l * DI + d];
            float E = __expf(-t);
#pragma unroll
            for (int s = 0; s < DS; s++) {
                float p = 1.f, base = E;
                int m = nn[s];
                while (m) { if (m & 1) p *= base; base *= base; m >>= 1; }
                if (ff[s] != 0.f) p *= __expf(-t * ff[s]);
                acc[s] = fmaf(w * p, brow[s], acc[s]);
            }
            t += dt;
        }
    }
#pragma unroll
    for (int s = 0; s < DS; s++)
        g_hpart[(size_t)c * DI * DS + d * DS + s] = acc[s];
}

__global__ void k_hred() {
    int i = blockIdx.x * blockDim.x + threadIdx.x;
    if (i >= DI * DS) return;
    float s = 0.f;
#pragma unroll
    for (int c = 0; c < NCHUNK; c++) s += g_hpart[(size_t)c * DI * DS + i];
    g_h[i] = s;
}

// ---------------- last-step GEMVs ----------------
__global__ void k_zlast(const float* __restrict__ fe, const float* __restrict__ inw) {
    int gw = (blockIdx.x * blockDim.x + threadIdx.x) / 32;
    int lane = threadIdx.x % 32;
    if (gw >= DI) return;
    const float* a = fe + (size_t)(L - 1) * DM;
    const float* w = inw + (size_t)(DI + gw) * DM;
    float s = 0.f;
    for (int m = lane; m < DM; m += 32) s = fmaf(a[m], w[m], s);
#pragma unroll
    for (int o = 16; o; o >>= 1) s += __shfl_xor_sync(0xFFFFFFFFu, s, o);
    if (lane == 0) g_z[gw] = s;
}

__global__ void k_clast(const float* __restrict__ xpw) {
    int s = threadIdx.x / 32;
    int lane = threadIdx.x % 32;
    if (s >= DS) return;
    const float* a = g_xc + (size_t)(L - 1) * DI;
    const float* w = xpw + (size_t)(DTR + DS + s) * DI;
    float acc = 0.f;
    for (int d = lane; d < DI; d += 32) acc = fmaf(a[d], w[d], acc);
#pragma unroll
    for (int o = 16; o; o >>= 1) acc += __shfl_xor_sync(0xFFFFFFFFu, acc, o);
    if (lane == 0) g_C[s] = acc;
}

__global__ void k_y(const float* __restrict__ Dp) {
    int d = blockIdx.x * blockDim.x + threadIdx.x;
    if (d >= DI) return;
    float s = 0.f;
#pragma unroll
    for (int j = 0; j < DS; j++) s = fmaf(g_h[d * DS + j], g_C[j], s);
    float y = s + g_xc[(size_t)(L - 1) * DI + d] * Dp[d];
    float z = g_z[d];
    y *= z / (1.f + __expf(-z));
    g_y[d] = y;
}

__global__ void k_out1(const float* __restrict__ outw) {
    int e = blockIdx.x;
    const float* w = outw + (size_t)e * DI;
    float s = 0.f;
    for (int d = threadIdx.x; d < DI; d += 256) s = fmaf(g_y[d], w[d], s);
    __shared__ float red[256];
    red[threadIdx.x] = s;
    __syncthreads();
    for (int o = 128; o >= 1; o >>= 1) {
        if (threadIdx.x < o) red[threadIdx.x] += red[threadIdx.x + o];
        __syncthreads();
    }
    if (threadIdx.x == 0) g_outraw[e] = red[0];
}

__global__ void k_out2(float* __restrict__ out) {
    int t = threadIdx.x;
    float v = g_outraw[t];
    __shared__ float red[768];
    red[t] = v * v;
    __syncthreads();
    if (t < 256) red[t] += red[t + 256] + red[t + 512];
    __syncthreads();
    for (int o = 128; o >= 1; o >>= 1) {
        if (t < o) red[t] += red[t + o];
        __syncthreads();
    }
    float denom = fmaxf(sqrtf(red[0]), 1e-12f);
    out[t] = v / denom;
}

// ---------------- launch ----------------
extern "C" void kernel_launch(void* const* d_in, const int* in_sizes, int n_in,
                              void* d_out, int out_size) {
    const float* fe    = (const float*)d_in[0];
    const float* inw   = (const float*)d_in[1];
    const float* convw = (const float*)d_in[2];
    const float* convb = (const float*)d_in[3];
    const float* xpw   = (const float*)d_in[4];
    const float* dtw   = (const float*)d_in[5];
    const float* dtb   = (const float*)d_in[6];
    const float* alog  = (const float*)d_in[7];
    const float* Dp    = (const float*)d_in[8];
    const float* outw  = (const float*)d_in[9];
    float* out = (float*)d_out;

    k_init<<<1, 32>>>();
    k_prep<<<96, 256>>>(alog);
    k_cvt_fe<<<(L * DM + 255) / 256, 256>>>(fe);
    k_cvt_w<<<(DI * DM + 255) / 256, 256>>>(inw);

    k_gemm1_wmma<<<dim3(DI / 128, L / 128), 256>>>();

    k_conv<<<(DI * (L / 4) + 255) / 256, 256>>>(convw, convb);

    k_gemm2<<<dim3(KS2, L / 64), 256>>>(xpw);
    k_xdblred<<<(L * 64 + 255) / 256, 256>>>();
    k_gemm3<<<dim3(DI / 128, L / 128), 256>>>(dtw, dtb);

    k_chunksum<<<(NCHUNK * DI + 255) / 256, 256>>>();
    k_chunksuf<<<(DI + 255) / 256, 256>>>();
    k_scan<<<dim3(DI / 128, NCHUNK), 128>>>();
    k_hred<<<(DI * DS + 255) / 256, 256>>>();

    k_zlast<<<(DI * 32 + 255) / 256, 256>>>(fe, inw);
    k_clast<<<1, 512>>>(xpw);
    k_y<<<(DI + 255) / 256, 256>>>(Dp);
    k_out1<<<DM, 256>>>(outw);
    k_out2<<<1, 768>>>(out);
}

// round 8
// speedup vs baseline: 1.7777x; 1.0705x over previous
#include <cuda_runtime.h>
#include <cuda_bf16.h>
#include <mma.h>
#include <math.h>
#include <stdint.h>

using namespace nvcuda;

#define L      4096
#define DM     768
#define DI     1536
#define DS     16
#define DTR    48
#define NCHUNK 64
#define CHUNK  (L / NCHUNK)          // 64
#define KP     (3 * DM)              // 2304: [ah|ah|al] x [bh|bl|bh]
#define KS2    6
#define KC2    (DI / KS2)

// ---------------- scratch ----------------
__device__ float g_xc_pre[L * DI];
__device__ float g_xc[L * DI];
__device__ float g_dt[L * DI];
__device__ float g_xdbl[L * 64];
__device__ float g_xdbl_part[KS2][L * 64];
__device__ float g_csum[NCHUNK * DI];
__device__ float g_csuf[NCHUNK * DI];
__device__ float g_hpart[NCHUNK * DI * DS];
__device__ float g_h[DI * DS];
__device__ float g_C[DS];
__device__ float g_z[DI];
__device__ float g_y[DI];
__device__ float g_outraw[DM];
__device__ int   g_nexp[DI * DS];
__device__ float g_fexp[DI * DS];
__device__ int   g_fast = 1;                 // static init; atomicAnd is idempotent per fixed inputs
__device__ __nv_bfloat16 g_feS[L * KP];
__device__ __nv_bfloat16 g_wS[DI * KP];

__device__ __forceinline__ uint32_t smem_u32(const void* p) {
    uint32_t a;
    asm("{ .reg .u64 t; cvta.to.shared.u64 t, %1; cvt.u32.u64 %0, t; }" : "=r"(a) : "l"(p));
    return a;
}

// ---------------- prep ----------------
__global__ void k_prep(const float* __restrict__ alog) {
    int i = blockIdx.x * blockDim.x + threadIdx.x;
    if (i >= DI * DS) return;
    int s = i % DS;
    float a = expf(alog[i]);
    int   n = (int)rintf(a);
    float f;
    bool isint = (n >= 0) && (fabsf(a - (float)n) <= 1e-4f * fmaxf(1.f, a));
    if (isint) { f = 0.f; }
    else { n = (int)floorf(a); f = a - (float)n; if (n < 0) { n = 0; f = a; } }
    g_nexp[i] = n;
    g_fexp[i] = f;
    if (!(isint && n == s + 1)) atomicAnd(&g_fast, 0);
}

// ---------------- fused split conversions ----------------
__global__ void k_cvt(const float* __restrict__ fe, const float* __restrict__ inw) {
    int i = blockIdx.x * blockDim.x + threadIdx.x;
    if (i < L * DM) {
        float x = fe[i];
        __nv_bfloat16 h = __float2bfloat16(x);
        __nv_bfloat16 lo = __float2bfloat16(x - __bfloat162float(h));
        int row = i / DM, col = i % DM;
        size_t base = (size_t)row * KP;
        g_feS[base + col]          = h;
        g_feS[base + DM + col]     = h;
        g_feS[base + 2 * DM + col] = lo;
    } else {
        int j = i - L * DM;
        if (j >= DI * DM) return;
        float x = inw[j];
        __nv_bfloat16 h = __float2bfloat16(x);
        __nv_bfloat16 lo = __float2bfloat16(x - __bfloat162float(h));
        int row = j / DM, col = j % DM;
        size_t base = (size_t)row * KP;
        g_wS[base + col]          = h;
        g_wS[base + DM + col]     = lo;
        g_wS[base + 2 * DM + col] = h;
    }
}

// ---------------- WMMA GEMM1, 3-stage cp.async pipeline ----------------
#define G1_BK 32
#define G1_LD 40
#define G1_NT (KP / G1_BK)           // 72
#define G1_STAGE_B (128 * G1_LD * 2) // bytes per stage per array (10240)
#define G1_SMEM (6 * G1_STAGE_B)     // 61440

__global__ void __launch_bounds__(256)
k_gemm1_wmma() {
    extern __shared__ __align__(16) char dsm[];
    __nv_bfloat16 (*sA)[128][G1_LD] = reinterpret_cast<__nv_bfloat16 (*)[128][G1_LD]>(dsm);
    __nv_bfloat16 (*sB)[128][G1_LD] = reinterpret_cast<__nv_bfloat16 (*)[128][G1_LD]>(dsm + 3 * G1_STAGE_B);
    const int tid = threadIdx.x;
    const int wid = tid >> 5;
    const int wm = wid & 3;
    const int wn = wid >> 2;
    const int m0 = blockIdx.y * 128;
    const int n0 = blockIdx.x * 128;

    wmma::fragment<wmma::accumulator, 16, 16, 16, float> acc[2][4];
#pragma unroll
    for (int i = 0; i < 2; i++)
#pragma unroll
        for (int j = 0; j < 4; j++) wmma::fill_fragment(acc[i][j], 0.f);

    const int r0 = tid >> 2;
    const int c0 = (tid & 3) << 3;

#define G1_ISSUE(st, k0)                                                              \
    do {                                                                              \
        _Pragma("unroll")                                                             \
        for (int h = 0; h < 2; h++) {                                                 \
            int r = r0 + h * 64;                                                      \
            uint32_t sa = smem_u32(&sA[st][r][c0]);                                   \
            uint32_t sb = smem_u32(&sB[st][r][c0]);                                   \
            const void* ga = &g_feS[(size_t)(m0 + r) * KP + (k0) + c0];               \
            const void* gb = &g_wS[(size_t)(n0 + r) * KP + (k0) + c0];                \
            asm volatile("cp.async.cg.shared.global [%0], [%1], 16;" :: "r"(sa), "l"(ga)); \
            asm volatile("cp.async.cg.shared.global [%0], [%1], 16;" :: "r"(sb), "l"(gb)); \
        }                                                                             \
        asm volatile("cp.async.commit_group;");                                       \
    } while (0)

    G1_ISSUE(0, 0);
    G1_ISSUE(1, G1_BK);
    for (int t = 0; t < G1_NT; t++) {
        if (t + 1 < G1_NT) asm volatile("cp.async.wait_group 1;");
        else               asm volatile("cp.async.wait_group 0;");
        __syncthreads();
        if (t + 2 < G1_NT) G1_ISSUE((t + 2) % 3, (t + 2) * G1_BK);
        const int st = t % 3;
#pragma unroll
        for (int kk = 0; kk < G1_BK; kk += 16) {
            wmma::fragment<wmma::matrix_a, 16, 16, 16, __nv_bfloat16, wmma::row_major> fa[2];
            wmma::fragment<wmma::matrix_b, 16, 16, 16, __nv_bfloat16, wmma::col_major> fb[4];
#pragma unroll
            for (int i = 0; i < 2; i++)
                wmma::load_matrix_sync(fa[i], &sA[st][wm * 32 + i * 16][kk], G1_LD);
#pragma unroll
            for (int j = 0; j < 4; j++)
                wmma::load_matrix_sync(fb[j], &sB[st][wn * 64 + j * 16][kk], G1_LD);
#pragma unroll
            for (int i = 0; i < 2; i++)
#pragma unroll
                for (int j = 0; j < 4; j++)
                    wmma::mma_sync(acc[i][j], fa[i], fb[j], acc[i][j]);
        }
    }
    __syncthreads();
#pragma unroll
    for (int i = 0; i < 2; i++)
#pragma unroll
        for (int j = 0; j < 4; j++)
            wmma::store_matrix_sync(
                &g_xc_pre[(size_t)(m0 + wm * 32 + i * 16) * DI + n0 + wn * 64 + j * 16],
                acc[i][j], DI, wmma::mem_row_major);
}

// ---------------- SIMT SGEMM body (NT); CSUM fuses per-chunk dt sums ------
template<int BM, int BN, int BK, int TM, int TN, bool SOFTPLUS>
__device__ __forceinline__ void sgemm_nt_body(
        int kbeg, int kend,
        const float* __restrict__ A, int lda,
        const float* __restrict__ B, int ldb,
        float* __restrict__ C, int ldc,
        const float* __restrict__ bias,
        int m0, int n0) {
    constexpr int THREADS = (BM / TM) * (BN / TN);
    __shared__ float As[BK][BM];
    __shared__ float Bs[BK][BN];
    const int tid = threadIdx.x;
    const int tx = tid % (BN / TN);
    const int ty = tid / (BN / TN);

    float acc[TM][TN];
#pragma unroll
    for (int i = 0; i < TM; i++)
#pragma unroll
        for (int j = 0; j < TN; j++) acc[i][j] = 0.f;

    for (int k0 = kbeg; k0 < kend; k0 += BK) {
#pragma unroll
        for (int i = tid; i < BM * (BK / 4); i += THREADS) {
            int r = i / (BK / 4), c = (i % (BK / 4)) * 4;
            float4 v = *reinterpret_cast<const float4*>(A + (size_t)(m0 + r) * lda + k0 + c);
            As[c + 0][r] = v.x; As[c + 1][r] = v.y; As[c + 2][r] = v.z; As[c + 3][r] = v.w;
        }
#pragma unroll
        for (int i = tid; i < BN * (BK / 4); i += THREADS) {
            int r = i / (BK / 4), c = (i % (BK / 4)) * 4;
            float4 v = *reinterpret_cast<const float4*>(B + (size_t)(n0 + r) * ldb + k0 + c);
            Bs[c + 0][r] = v.x; Bs[c + 1][r] = v.y; Bs[c + 2][r] = v.z; Bs[c + 3][r] = v.w;
        }
        __syncthreads();
#pragma unroll
        for (int kk = 0; kk < BK; kk++) {
            float ra[TM], rb[TN];
#pragma unroll
            for (int i = 0; i < TM; i += 4) {
                float4 v = *reinterpret_cast<const float4*>(&As[kk][ty * TM + i]);
                ra[i] = v.x; ra[i + 1] = v.y; ra[i + 2] = v.z; ra[i + 3] = v.w;
            }
#pragma unroll
            for (int j = 0; j < TN; j += 4) {
                float4 v = *reinterpret_cast<const float4*>(&Bs[kk][tx * TN + j]);
                rb[j] = v.x; rb[j + 1] = v.y; rb[j + 2] = v.z; rb[j + 3] = v.w;
            }
#pragma unroll
            for (int i = 0; i < TM; i++)
#pragma unroll
                for (int j = 0; j < TN; j++) acc[i][j] = fmaf(ra[i], rb[j], acc[i][j]);
        }
        __syncthreads();
    }

    if (!SOFTPLUS) {
#pragma unroll
        for (int i = 0; i < TM; i++) {
#pragma unroll
            for (int j = 0; j < TN; j += 4) {
                float4 v = make_float4(acc[i][j], acc[i][j + 1], acc[i][j + 2], acc[i][j + 3]);
                *reinterpret_cast<float4*>(C + (size_t)(m0 + ty * TM + i) * ldc + n0 + tx * TN + j) = v;
            }
        }
    } else {
        // gemm3 path: softplus epilogue + fused per-chunk column sums
        __shared__ float s_cs[16][128];
        float colsum[TN];
#pragma unroll
        for (int j = 0; j < TN; j++) colsum[j] = 0.f;
#pragma unroll
        for (int i = 0; i < TM; i++) {
#pragma unroll
            for (int j = 0; j < TN; j += 4) {
                float vv[4];
                int col = n0 + tx * TN + j;
#pragma unroll
                for (int t = 0; t < 4; t++) {
                    float x = acc[i][j + t] + bias[col + t];
                    vv[t] = fmaxf(x, 0.f) + log1pf(__expf(-fabsf(x)));
                    colsum[j + t] += vv[t];
                }
                float4 v = make_float4(vv[0], vv[1], vv[2], vv[3]);
                *reinterpret_cast<float4*>(C + (size_t)(m0 + ty * TM + i) * ldc + n0 + tx * TN + j) = v;
            }
        }
#pragma unroll
        for (int j = 0; j < TN; j++) s_cs[ty][tx * TN + j] = colsum[j];
        __syncthreads();
        // 2 chunks of 64 rows per CTA (ty 0-7 / 8-15); 256 threads -> 2x128 outputs
        int h = tid >> 7, col = tid & 127;
        float s = 0.f;
#pragma unroll
        for (int q = 0; q < 8; q++) s += s_cs[h * 8 + q][col];
        g_csum[(size_t)(blockIdx.y * 2 + h) * DI + n0 + col] = s;
    }
}

__global__ void __launch_bounds__(256)
k_gemm2(const float* __restrict__ xpw) {
    int ck = blockIdx.x;
    sgemm_nt_body<64, 64, 16, 4, 4, false>(
        ck * KC2, (ck + 1) * KC2,
        g_xc, DI, xpw, DI, g_xdbl_part[ck], 64, nullptr,
        blockIdx.y * 64, 0);
}

__global__ void k_xdblred() {
    int i = blockIdx.x * blockDim.x + threadIdx.x;
    if (i >= L * 64) return;
    float s = 0.f;
#pragma unroll
    for (int c = 0; c < KS2; c++) s += g_xdbl_part[c][i];
    g_xdbl[i] = s;
}

__global__ void __launch_bounds__(256)
k_gemm3(const float* __restrict__ dtw, const float* __restrict__ dtb) {
    sgemm_nt_body<128, 128, 16, 8, 8, true>(
        0, DTR, g_xdbl, 64, dtw, DTR, g_dt, DI, dtb,
        blockIdx.y * 128, blockIdx.x * 128);
}

// ---------------- depthwise causal conv(4) + bias + silu ----------------
__global__ void k_conv(const float* __restrict__ w, const float* __restrict__ b) {
    int idx = blockIdx.x * blockDim.x + threadIdx.x;
    if (idx >= DI * (L / 4)) return;
    int d = idx % DI, g = idx / DI;
    int l0 = g * 4;
    float w0 = w[d * 4 + 0], w1 = w[d * 4 + 1], w2 = w[d * 4 + 2], w3 = w[d * 4 + 3];
    float bb = b[d];
    float x[7];
#pragma unroll
    for (int t = 0; t < 7; t++) {
        int l = l0 - 3 + t;
        x[t] = (l >= 0) ? g_xc_pre[(size_t)l * DI + d] : 0.f;
    }
#pragma unroll
    for (int t = 0; t < 4; t++) {
        float s = bb;
        s = fmaf(w0, x[t], s); s = fmaf(w1, x[t + 1], s);
        s = fmaf(w2, x[t + 2], s); s = fmaf(w3, x[t + 3], s);
        g_xc[(size_t)(l0 + t) * DI + d] = s / (1.f + __expf(-s));
    }
}

// ---------------- suffix over chunk sums ----------------
__global__ void k_chunksuf() {
    int d = blockIdx.x * blockDim.x + threadIdx.x;
    if (d >= DI) return;
    double t = 0.0;
    for (int c = NCHUNK - 1; c >= 0; --c) {
        g_csuf[c * DI + d] = (float)t;
        t += (double)g_csum[c * DI + d];
    }
}

// ---------------- parallel closed-form scan ----------------
__global__ void k_scan() {
    int d = blockIdx.x * 128 + threadIdx.x;
    int c = blockIdx.y;
    float t = g_csuf[c * DI + d];
    float acc[DS];
#pragma unroll
    for (int s = 0; s < DS; s++) acc[s] = 0.f;
    const int l0 = c * CHUNK;
    const bool fast = (g_fast != 0);

    if (fast) {
        for (int l = l0 + CHUNK - 1; l >= l0; --l) {
            const float* brow = g_xdbl + (size_t)l * 64 + DTR;
            float4 q0 = *reinterpret_cast<const float4*>(brow + 0);
            float4 q1 = *reinterpret_cast<const float4*>(brow + 4);
            float4 q2 = *reinterpret_cast<const float4*>(brow + 8);
            float4 q3 = *reinterpret_cast<const float4*>(brow + 12);
            float bv[16] = {q0.x, q0.y, q0.z, q0.w, q1.x, q1.y, q1.z, q1.w,
                            q2.x, q2.y, q2.z, q2.w, q3.x, q3.y, q3.z, q3.w};
            float dt = g_dt[(size_t)l * DI + d];
            float w  = dt * g_xc[(size_t)l * DI + d];
            float E = __expf(-t);
            float p = 1.f;
#pragma unroll
            for (int s = 0; s < DS; s++) { p *= E; acc[s] = fmaf(w * p, bv[s], acc[s]); }
            t += dt;
        }
    } else {
        int nn[DS]; float ff[DS];
#pragma unroll
        for (int s = 0; s < DS; s++) { nn[s] = g_nexp[d * DS + s]; ff[s] = g_fexp[d * DS + s]; }
        for (int l = l0 + CHUNK - 1; l >= l0; --l) {
            const float* brow = g_xdbl + (size_t)l * 64 + DTR;
            float dt = g_dt[(size_t)l * DI + d];
            float w  = dt * g_xc[(size_t)l * DI + d];
            float E = __expf(-t);
#pragma unroll
            for (int s = 0; s < DS; s++) {
                float p = 1.f, base = E;
                int m = nn[s];
                while (m) { if (m & 1) p *= base; base *= base; m >>= 1; }
                if (ff[s] != 0.f) p *= __expf(-t * ff[s]);
                acc[s] = fmaf(w * p, brow[s], acc[s]);
            }
            t += dt;
        }
    }
#pragma unroll
    for (int s = 0; s < DS; s++)
        g_hpart[(size_t)c * DI * DS + d * DS + s] = acc[s];
}

__global__ void k_hred() {
    int i = blockIdx.x * blockDim.x + threadIdx.x;
    if (i >= DI * DS) return;
    float s = 0.f;
#pragma unroll
    for (int c = 0; c < NCHUNK; c++) s += g_hpart[(size_t)c * DI * DS + i];
    g_h[i] = s;
}

// ---------------- fused last-step GEMVs (z and C) ----------------
__global__ void k_zc(const float* __restrict__ fe, const float* __restrict__ inw,
                     const float* __restrict__ xpw) {
    int gw = (blockIdx.x * blockDim.x + threadIdx.x) / 32;
    int lane = threadIdx.x % 32;
    if (gw < DI) {
        const float* a = fe + (size_t)(L - 1) * DM;
        const float* w = inw + (size_t)(DI + gw) * DM;
        float s = 0.f;
        for (int m = lane; m < DM; m += 32) s = fmaf(a[m], w[m], s);
#pragma unroll
        for (int o = 16; o; o >>= 1) s += __shfl_xor_sync(0xFFFFFFFFu, s, o);
        if (lane == 0) g_z[gw] = s;
    } else if (gw < DI + DS) {
        int sidx = gw - DI;
        const float* a = g_xc + (size_t)(L - 1) * DI;
        const float* w = xpw + (size_t)(DTR + DS + sidx) * DI;
        float acc = 0.f;
        for (int d = lane; d < DI; d += 32) acc = fmaf(a[d], w[d], acc);
#pragma unroll
        for (int o = 16; o; o >>= 1) acc += __shfl_xor_sync(0xFFFFFFFFu, acc, o);
        if (lane == 0) g_C[sidx] = acc;
    }
}

__global__ void k_y(const float* __restrict__ Dp) {
    int d = blockIdx.x * blockDim.x + threadIdx.x;
    if (d >= DI) return;
    float s = 0.f;
#pragma unroll
    for (int j = 0; j < DS; j++) s = fmaf(g_h[d * DS + j], g_C[j], s);
    float y = s + g_xc[(size_t)(L - 1) * DI + d] * Dp[d];
    float z = g_z[d];
    y *= z / (1.f + __expf(-z));
    g_y[d] = y;
}

__global__ void k_out1(const float* __restrict__ outw) {
    int e = blockIdx.x;
    const float* w = outw + (size_t)e * DI;
    float s = 0.f;
    for (int d = threadIdx.x; d < DI; d += 256) s = fmaf(g_y[d], w[d], s);
    __shared__ float red[256];
    red[threadIdx.x] = s;
    __syncthreads();
    for (int o = 128; o >= 1; o >>= 1) {
        if (threadIdx.x < o) red[threadIdx.x] += red[threadIdx.x + o];
        __syncthreads();
    }
    if (threadIdx.x == 0) g_outraw[e] = red[0];
}

__global__ void k_out2(float* __restrict__ out) {
    int t = threadIdx.x;
    float v = g_outraw[t];
    __shared__ float red[768];
    red[t] = v * v;
    __syncthreads();
    if (t < 256) red[t] += red[t + 256] + red[t + 512];
    __syncthreads();
    for (int o = 128; o >= 1; o >>= 1) {
        if (t < o) red[t] += red[t + o];
        __syncthreads();
    }
    float denom = fmaxf(sqrtf(red[0]), 1e-12f);
    out[t] = v / denom;
}

// ---------------- launch ----------------
extern "C" void kernel_launch(void* const* d_in, const int* in_sizes, int n_in,
                              void* d_out, int out_size) {
    const float* fe    = (const float*)d_in[0];
    const float* inw   = (const float*)d_in[1];
    const float* convw = (const float*)d_in[2];
    const float* convb = (const float*)d_in[3];
    const float* xpw   = (const float*)d_in[4];
    const float* dtw   = (const float*)d_in[5];
    const float* dtb   = (const float*)d_in[6];
    const float* alog  = (const float*)d_in[7];
    const float* Dp    = (const float*)d_in[8];
    const float* outw  = (const float*)d_in[9];
    float* out = (float*)d_out;

    cudaFuncSetAttribute(k_gemm1_wmma, cudaFuncAttributeMaxDynamicSharedMemorySize, G1_SMEM);

    k_prep<<<96, 256>>>(alog);
    k_cvt<<<((L + DI) * DM + 255) / 256, 256>>>(fe, inw);

    k_gemm1_wmma<<<dim3(DI / 128, L / 128), 256, G1_SMEM>>>();

    k_conv<<<(DI * (L / 4) + 255) / 256, 256>>>(convw, convb);

    k_gemm2<<<dim3(KS2, L / 64), 256>>>(xpw);
    k_xdblred<<<(L * 64 + 255) / 256, 256>>>();
    k_gemm3<<<dim3(DI / 128, L / 128), 256>>>(dtw, dtb);   // also writes g_csum

    k_chunksuf<<<(DI + 255) / 256, 256>>>();
    k_scan<<<dim3(DI / 128, NCHUNK), 128>>>();
    k_hred<<<(DI * DS + 255) / 256, 256>>>();

    k_zc<<<((DI + DS) * 32 + 255) / 256, 256>>>(fe, inw, xpw);
    k_y<<<(DI + 255) / 256, 256>>>(Dp);
    k_out1<<<DM, 256>>>(outw);
    k_out2<<<1, 768>>>(out);
}

// round 9
// speedup vs baseline: 1.7998x; 1.0124x over previous
#include <cuda_runtime.h>
#include <cuda_bf16.h>
#include <mma.h>
#include <math.h>
#include <stdint.h>

using namespace nvcuda;

#define L      4096
#define DM     768
#define DI     1536
#define DS     16
#define DTR    48
#define NCHUNK 64
#define CHUNK  (L / NCHUNK)          // 64
#define KP     (3 * DM)              // 2304: [ah|ah|al] x [bh|bl|bh]
#define KS2    6
#define KC2    (DI / KS2)

// ---------------- scratch ----------------
__device__ float g_xc_pre[L * DI];
__device__ float g_xc[L * DI];
__device__ float g_dt[L * DI];
__device__ float g_xdbl[L * 64];
__device__ float g_xdbl_part[KS2][L * 64];
__device__ float g_csum[NCHUNK * DI];
__device__ float g_csuf[NCHUNK * DI];
__device__ float g_hpart[NCHUNK * DI * DS];
__device__ float g_h[DI * DS];
__device__ float g_C[DS];
__device__ float g_z[DI];
__device__ float g_y[DI];
__device__ float g_outraw[DM];
__device__ int   g_nexp[DI * DS];
__device__ float g_fexp[DI * DS];
__device__ int   g_fast = 1;
__device__ __nv_bfloat16 g_feS[L * KP];
__device__ __nv_bfloat16 g_wS[DI * KP];

__device__ __forceinline__ uint32_t smem_u32(const void* p) {
    uint32_t a;
    asm("{ .reg .u64 t; cvta.to.shared.u64 t, %1; cvt.u32.u64 %0, t; }" : "=r"(a) : "l"(p));
    return a;
}

// ---------------- prep ----------------
__global__ void k_prep(const float* __restrict__ alog) {
    int i = blockIdx.x * blockDim.x + threadIdx.x;
    if (i >= DI * DS) return;
    int s = i % DS;
    float a = expf(alog[i]);
    int   n = (int)rintf(a);
    float f;
    bool isint = (n >= 0) && (fabsf(a - (float)n) <= 1e-4f * fmaxf(1.f, a));
    if (isint) { f = 0.f; }
    else { n = (int)floorf(a); f = a - (float)n; if (n < 0) { n = 0; f = a; } }
    g_nexp[i] = n;
    g_fexp[i] = f;
    if (!(isint && n == s + 1)) atomicAnd(&g_fast, 0);
}

// ---------------- split conversions ----------------
__global__ void k_cvt_fe(const float* __restrict__ fe) {
    int i = blockIdx.x * blockDim.x + threadIdx.x;
    if (i >= L * DM) return;
    float x = fe[i];
    __nv_bfloat16 h = __float2bfloat16(x);
    __nv_bfloat16 lo = __float2bfloat16(x - __bfloat162float(h));
    int row = i / DM, col = i % DM;
    size_t base = (size_t)row * KP;
    g_feS[base + col]          = h;
    g_feS[base + DM + col]     = h;
    g_feS[base + 2 * DM + col] = lo;
}
__global__ void k_cvt_w(const float* __restrict__ inw) {
    int i = blockIdx.x * blockDim.x + threadIdx.x;
    if (i >= DI * DM) return;
    float x = inw[i];
    __nv_bfloat16 h = __float2bfloat16(x);
    __nv_bfloat16 lo = __float2bfloat16(x - __bfloat162float(h));
    int row = i / DM, col = i % DM;
    size_t base = (size_t)row * KP;
    g_wS[base + col]          = h;
    g_wS[base + DM + col]     = lo;
    g_wS[base + 2 * DM + col] = h;
}

// ---------------- WMMA GEMM1, 3-stage cp.async pipeline ----------------
#define G1_BK 32
#define G1_LD 40
#define G1_NT (KP / G1_BK)           // 72
#define G1_STAGE_B (128 * G1_LD * 2)
#define G1_SMEM (6 * G1_STAGE_B)     // 61440

__global__ void __launch_bounds__(256)
k_gemm1_wmma() {
    extern __shared__ __align__(16) char dsm[];
    __nv_bfloat16 (*sA)[128][G1_LD] = reinterpret_cast<__nv_bfloat16 (*)[128][G1_LD]>(dsm);
    __nv_bfloat16 (*sB)[128][G1_LD] = reinterpret_cast<__nv_bfloat16 (*)[128][G1_LD]>(dsm + 3 * G1_STAGE_B);
    const int tid = threadIdx.x;
    const int wid = tid >> 5;
    const int wm = wid & 3;
    const int wn = wid >> 2;
    const int m0 = blockIdx.y * 128;
    const int n0 = blockIdx.x * 128;

    wmma::fragment<wmma::accumulator, 16, 16, 16, float> acc[2][4];
#pragma unroll
    for (int i = 0; i < 2; i++)
#pragma unroll
        for (int j = 0; j < 4; j++) wmma::fill_fragment(acc[i][j], 0.f);

    const int r0 = tid >> 2;
    const int c0 = (tid & 3) << 3;

#define G1_ISSUE(st, k0)                                                              \
    do {                                                                              \
        _Pragma("unroll")                                                             \
        for (int h = 0; h < 2; h++) {                                                 \
            int r = r0 + h * 64;                                                      \
            uint32_t sa = smem_u32(&sA[st][r][c0]);                                   \
            uint32_t sb = smem_u32(&sB[st][r][c0]);                                   \
            const void* ga = &g_feS[(size_t)(m0 + r) * KP + (k0) + c0];               \
            const void* gb = &g_wS[(size_t)(n0 + r) * KP + (k0) + c0];                \
            asm volatile("cp.async.cg.shared.global [%0], [%1], 16;" :: "r"(sa), "l"(ga)); \
            asm volatile("cp.async.cg.shared.global [%0], [%1], 16;" :: "r"(sb), "l"(gb)); \
        }                                                                             \
        asm volatile("cp.async.commit_group;");                                       \
    } while (0)

    G1_ISSUE(0, 0);
    G1_ISSUE(1, G1_BK);
    for (int t = 0; t < G1_NT; t++) {
        if (t + 1 < G1_NT) asm volatile("cp.async.wait_group 1;");
        else               asm volatile("cp.async.wait_group 0;");
        __syncthreads();
        if (t + 2 < G1_NT) G1_ISSUE((t + 2) % 3, (t + 2) * G1_BK);
        const int st = t % 3;
#pragma unroll
        for (int kk = 0; kk < G1_BK; kk += 16) {
            wmma::fragment<wmma::matrix_a, 16, 16, 16, __nv_bfloat16, wmma::row_major> fa[2];
            wmma::fragment<wmma::matrix_b, 16, 16, 16, __nv_bfloat16, wmma::col_major> fb[4];
#pragma unroll
            for (int i = 0; i < 2; i++)
                wmma::load_matrix_sync(fa[i], &sA[st][wm * 32 + i * 16][kk], G1_LD);
#pragma unroll
            for (int j = 0; j < 4; j++)
                wmma::load_matrix_sync(fb[j], &sB[st][wn * 64 + j * 16][kk], G1_LD);
#pragma unroll
            for (int i = 0; i < 2; i++)
#pragma unroll
                for (int j = 0; j < 4; j++)
                    wmma::mma_sync(acc[i][j], fa[i], fb[j], acc[i][j]);
        }
    }
    __syncthreads();
#pragma unroll
    for (int i = 0; i < 2; i++)
#pragma unroll
        for (int j = 0; j < 4; j++)
            wmma::store_matrix_sync(
                &g_xc_pre[(size_t)(m0 + wm * 32 + i * 16) * DI + n0 + wn * 64 + j * 16],
                acc[i][j], DI, wmma::mem_row_major);
}

// ---------------- SIMT SGEMM body (NT); gemm3 fuses softplus + chunk sums --
template<int BM, int BN, int BK, int TM, int TN, bool SOFTPLUS>
__device__ __forceinline__ void sgemm_nt_body(
        int kbeg, int kend,
        const float* __restrict__ A, int lda,
        const float* __restrict__ B, int ldb,
        float* __restrict__ C, int ldc,
        const float* __restrict__ bias,
        int m0, int n0) {
    constexpr int THREADS = (BM / TM) * (BN / TN);
    __shared__ float As[BK][BM];
    __shared__ float Bs[BK][BN];
    const int tid = threadIdx.x;
    const int tx = tid % (BN / TN);
    const int ty = tid / (BN / TN);

    float acc[TM][TN];
#pragma unroll
    for (int i = 0; i < TM; i++)
#pragma unroll
        for (int j = 0; j < TN; j++) acc[i][j] = 0.f;

    for (int k0 = kbeg; k0 < kend; k0 += BK) {
#pragma unroll
        for (int i = tid; i < BM * (BK / 4); i += THREADS) {
            int r = i / (BK / 4), c = (i % (BK / 4)) * 4;
            float4 v = *reinterpret_cast<const float4*>(A + (size_t)(m0 + r) * lda + k0 + c);
            As[c + 0][r] = v.x; As[c + 1][r] = v.y; As[c + 2][r] = v.z; As[c + 3][r] = v.w;
        }
#pragma unroll
        for (int i = tid; i < BN * (BK / 4); i += THREADS) {
            int r = i / (BK / 4), c = (i % (BK / 4)) * 4;
            float4 v = *reinterpret_cast<const float4*>(B + (size_t)(n0 + r) * ldb + k0 + c);
            Bs[c + 0][r] = v.x; Bs[c + 1][r] = v.y; Bs[c + 2][r] = v.z; Bs[c + 3][r] = v.w;
        }
        __syncthreads();
#pragma unroll
        for (int kk = 0; kk < BK; kk++) {
            float ra[TM], rb[TN];
#pragma unroll
            for (int i = 0; i < TM; i += 4) {
                float4 v = *reinterpret_cast<const float4*>(&As[kk][ty * TM + i]);
                ra[i] = v.x; ra[i + 1] = v.y; ra[i + 2] = v.z; ra[i + 3] = v.w;
            }
#pragma unroll
            for (int j = 0; j < TN; j += 4) {
                float4 v = *reinterpret_cast<const float4*>(&Bs[kk][tx * TN + j]);
                rb[j] = v.x; rb[j + 1] = v.y; rb[j + 2] = v.z; rb[j + 3] = v.w;
            }
#pragma unroll
            for (int i = 0; i < TM; i++)
#pragma unroll
                for (int j = 0; j < TN; j++) acc[i][j] = fmaf(ra[i], rb[j], acc[i][j]);
        }
        __syncthreads();
    }

    if (!SOFTPLUS) {
#pragma unroll
        for (int i = 0; i < TM; i++) {
#pragma unroll
            for (int j = 0; j < TN; j += 4) {
                float4 v = make_float4(acc[i][j], acc[i][j + 1], acc[i][j + 2], acc[i][j + 3]);
                *reinterpret_cast<float4*>(C + (size_t)(m0 + ty * TM + i) * ldc + n0 + tx * TN + j) = v;
            }
        }
    } else {
        __shared__ float s_cs[16][128];
        float colsum[TN];
#pragma unroll
        for (int j = 0; j < TN; j++) colsum[j] = 0.f;
#pragma unroll
        for (int i = 0; i < TM; i++) {
#pragma unroll
            for (int j = 0; j < TN; j += 4) {
                float vv[4];
                int col = n0 + tx * TN + j;
#pragma unroll
                for (int t = 0; t < 4; t++) {
                    float x = acc[i][j + t] + bias[col + t];
                    vv[t] = fmaxf(x, 0.f) + log1pf(__expf(-fabsf(x)));
                    colsum[j + t] += vv[t];
                }
                float4 v = make_float4(vv[0], vv[1], vv[2], vv[3]);
                *reinterpret_cast<float4*>(C + (size_t)(m0 + ty * TM + i) * ldc + n0 + tx * TN + j) = v;
            }
        }
#pragma unroll
        for (int j = 0; j < TN; j++) s_cs[ty][tx * TN + j] = colsum[j];
        __syncthreads();
        int h = tid >> 7, col = tid & 127;
        float s = 0.f;
#pragma unroll
        for (int q = 0; q < 8; q++) s += s_cs[h * 8 + q][col];
        g_csum[(size_t)(blockIdx.y * 2 + h) * DI + n0 + col] = s;
    }
}

__global__ void __launch_bounds__(256)
k_gemm2(const float* __restrict__ xpw) {
    int ck = blockIdx.x;
    sgemm_nt_body<64, 64, 16, 4, 4, false>(
        ck * KC2, (ck + 1) * KC2,
        g_xc, DI, xpw, DI, g_xdbl_part[ck], 64, nullptr,
        blockIdx.y * 64, 0);
}

__global__ void k_xdblred() {
    int i = blockIdx.x * blockDim.x + threadIdx.x;
    if (i >= L * 64) return;
    float s = 0.f;
#pragma unroll
    for (int c = 0; c < KS2; c++) s += g_xdbl_part[c][i];
    g_xdbl[i] = s;
}

__global__ void __launch_bounds__(256)
k_gemm3(const float* __restrict__ dtw, const float* __restrict__ dtb) {
    sgemm_nt_body<128, 128, 16, 8, 8, true>(
        0, DTR, g_xdbl, 64, dtw, DTR, g_dt, DI, dtb,
        blockIdx.y * 128, blockIdx.x * 128);
}

// ---------------- depthwise causal conv(4) + bias + silu (4d x 4l tiles) ---
__global__ void k_conv(const float* __restrict__ w, const float* __restrict__ b) {
    int idx = blockIdx.x * blockDim.x + threadIdx.x;
    if (idx >= (L / 4) * (DI / 4)) return;
    int dq = idx % (DI / 4);
    int g  = idx / (DI / 4);
    int d0 = dq * 4, l0 = g * 4;
    const float4* wp = reinterpret_cast<const float4*>(w) + d0;   // w[d][0..3]
    float4 w0 = wp[0], w1 = wp[1], w2 = wp[2], w3 = wp[3];
    float4 bb = *reinterpret_cast<const float4*>(b + d0);
    float4 x[7];
#pragma unroll
    for (int t = 0; t < 7; t++) {
        int l = l0 - 3 + t;
        x[t] = (l >= 0) ? *reinterpret_cast<const float4*>(&g_xc_pre[(size_t)l * DI + d0])
                        : make_float4(0.f, 0.f, 0.f, 0.f);
    }
#pragma unroll
    for (int t = 0; t < 4; t++) {
        float4 s;
        s.x = bb.x; s.y = bb.y; s.z = bb.z; s.w = bb.w;
        s.x = fmaf(w0.x, x[t].x, s.x); s.x = fmaf(w0.y, x[t+1].x, s.x); s.x = fmaf(w0.z, x[t+2].x, s.x); s.x = fmaf(w0.w, x[t+3].x, s.x);
        s.y = fmaf(w1.x, x[t].y, s.y); s.y = fmaf(w1.y, x[t+1].y, s.y); s.y = fmaf(w1.z, x[t+2].y, s.y); s.y = fmaf(w1.w, x[t+3].y, s.y);
        s.z = fmaf(w2.x, x[t].z, s.z); s.z = fmaf(w2.y, x[t+1].z, s.z); s.z = fmaf(w2.z, x[t+2].z, s.z); s.z = fmaf(w2.w, x[t+3].z, s.z);
        s.w = fmaf(w3.x, x[t].w, s.w); s.w = fmaf(w3.y, x[t+1].w, s.w); s.w = fmaf(w3.z, x[t+2].w, s.w); s.w = fmaf(w3.w, x[t+3].w, s.w);
        s.x = s.x / (1.f + __expf(-s.x));
        s.y = s.y / (1.f + __expf(-s.y));
        s.z = s.z / (1.f + __expf(-s.z));
        s.w = s.w / (1.f + __expf(-s.w));
        *reinterpret_cast<float4*>(&g_xc[(size_t)(l0 + t) * DI + d0]) = s;
    }
}

// ---------------- suffix over chunk sums ----------------
__global__ void k_chunksuf() {
    int d = blockIdx.x * blockDim.x + threadIdx.x;
    if (d >= DI) return;
    double t = 0.0;
    for (int c = NCHUNK - 1; c >= 0; --c) {
        g_csuf[c * DI + d] = (float)t;
        t += (double)g_csum[c * DI + d];
    }
}

// ---------------- parallel closed-form scan (B staged in smem) ------------
__global__ void k_scan() {
    __shared__ float sB[16][16];
    int tid = threadIdx.x;
    int d = blockIdx.x * 128 + tid;
    int c = blockIdx.y;
    float t = g_csuf[c * DI + d];
    float acc[DS];
#pragma unroll
    for (int s = 0; s < DS; s++) acc[s] = 0.f;
    const int l0 = c * CHUNK;
    const bool fast = (g_fast != 0);

    if (fast) {
        for (int lt = CHUNK - 16; lt >= 0; lt -= 16) {
            __syncthreads();
            {
                int i = tid * 2;
                int ll = i >> 4, ss = i & 15;
                float2 v = *reinterpret_cast<const float2*>(
                    &g_xdbl[(size_t)(l0 + lt + ll) * 64 + DTR + ss]);
                sB[ll][ss] = v.x; sB[ll][ss + 1] = v.y;
            }
            __syncthreads();
#pragma unroll
            for (int j = 15; j >= 0; --j) {
                int l = l0 + lt + j;
                float dt = g_dt[(size_t)l * DI + d];
                float w  = dt * g_xc[(size_t)l * DI + d];
                float E = __expf(-t);
                float p = 1.f;
#pragma unroll
                for (int s = 0; s < DS; s++) { p *= E; acc[s] = fmaf(w * p, sB[j][s], acc[s]); }
                t += dt;
            }
        }
    } else {
        int nn[DS]; float ff[DS];
#pragma unroll
        for (int s = 0; s < DS; s++) { nn[s] = g_nexp[d * DS + s]; ff[s] = g_fexp[d * DS + s]; }
        for (int l = l0 + CHUNK - 1; l >= l0; --l) {
            const float* brow = g_xdbl + (size_t)l * 64 + DTR;
            float dt = g_dt[(size_t)l * DI + d];
            float w  = dt * g_xc[(size_t)l * DI + d];
            float E = __expf(-t);
#pragma unroll
            for (int s = 0; s < DS; s++) {
                float p = 1.f, base = E;
                int m = nn[s];
                while (m) { if (m & 1) p *= base; base *= base; m >>= 1; }
                if (ff[s] != 0.f) p *= __expf(-t * ff[s]);
                acc[s] = fmaf(w * p, brow[s], acc[s]);
            }
            t += dt;
        }
    }
#pragma unroll
    for (int s = 0; s < DS; s++)
        g_hpart[(size_t)c * DI * DS + d * DS + s] = acc[s];
}

__global__ void k_hred() {
    int i = blockIdx.x * blockDim.x + threadIdx.x;
    if (i >= DI * DS) return;
    float s = 0.f;
#pragma unroll
    for (int c = 0; c < NCHUNK; c++) s += g_hpart[(size_t)c * DI * DS + i];
    g_h[i] = s;
}

// ---------------- fused last-step GEMVs (z and C) ----------------
__global__ void k_zc(const float* __restrict__ fe, const float* __restrict__ inw,
                     const float* __restrict__ xpw) {
    int gw = (blockIdx.x * blockDim.x + threadIdx.x) / 32;
    int lane = threadIdx.x % 32;
    if (gw < DI) {
        const float* a = fe + (size_t)(L - 1) * DM;
        const float* w = inw + (size_t)(DI + gw) * DM;
        float s = 0.f;
        for (int m = lane; m < DM; m += 32) s = fmaf(a[m], w[m], s);
#pragma unroll
        for (int o = 16; o; o >>= 1) s += __shfl_xor_sync(0xFFFFFFFFu, s, o);
        if (lane == 0) g_z[gw] = s;
    } else if (gw < DI + DS) {
        int sidx = gw - DI;
        const float* a = g_xc + (size_t)(L - 1) * DI;
        const float* w = xpw + (size_t)(DTR + DS + sidx) * DI;
        float acc = 0.f;
        for (int d = lane; d < DI; d += 32) acc = fmaf(a[d], w[d], acc);
#pragma unroll
        for (int o = 16; o; o >>= 1) acc += __shfl_xor_sync(0xFFFFFFFFu, acc, o);
        if (lane == 0) g_C[sidx] = acc;
    }
}

__global__ void k_y(const float* __restrict__ Dp) {
    int d = blockIdx.x * blockDim.x + threadIdx.x;
    if (d >= DI) return;
    float s = 0.f;
#pragma unroll
    for (int j = 0; j < DS; j++) s = fmaf(g_h[d * DS + j], g_C[j], s);
    float y = s + g_xc[(size_t)(L - 1) * DI + d] * Dp[d];
    float z = g_z[d];
    y *= z / (1.f + __expf(-z));
    g_y[d] = y;
}

__global__ void k_out1(const float* __restrict__ outw) {
    int e = blockIdx.x;
    const float* w = outw + (size_t)e * DI;
    float s = 0.f;
    for (int d = threadIdx.x; d < DI; d += 256) s = fmaf(g_y[d], w[d], s);
    __shared__ float red[256];
    red[threadIdx.x] = s;
    __syncthreads();
    for (int o = 128; o >= 1; o >>= 1) {
        if (threadIdx.x < o) red[threadIdx.x] += red[threadIdx.x + o];
        __syncthreads();
    }
    if (threadIdx.x == 0) g_outraw[e] = red[0];
}

__global__ void k_out2(float* __restrict__ out) {
    int t = threadIdx.x;
    float v = g_outraw[t];
    __shared__ float red[768];
    red[t] = v * v;
    __syncthreads();
    if (t < 256) red[t] += red[t + 256] + red[t + 512];
    __syncthreads();
    for (int o = 128; o >= 1; o >>= 1) {
        if (t < o) red[t] += red[t + o];
        __syncthreads();
    }
    float denom = fmaxf(sqrtf(red[0]), 1e-12f);
    out[t] = v / denom;
}

// ---------------- launch ----------------
extern "C" void kernel_launch(void* const* d_in, const int* in_sizes, int n_in,
                              void* d_out, int out_size) {
    const float* fe    = (const float*)d_in[0];
    const float* inw   = (const float*)d_in[1];
    const float* convw = (const float*)d_in[2];
    const float* convb = (const float*)d_in[3];
    const float* xpw   = (const float*)d_in[4];
    const float* dtw   = (const float*)d_in[5];
    const float* dtb   = (const float*)d_in[6];
    const float* alog  = (const float*)d_in[7];
    const float* Dp    = (const float*)d_in[8];
    const float* outw  = (const float*)d_in[9];
    float* out = (float*)d_out;

    cudaFuncSetAttribute(k_gemm1_wmma, cudaFuncAttributeMaxDynamicSharedMemorySize, G1_SMEM);

    k_prep<<<96, 256>>>(alog);                         // 1
    k_cvt_fe<<<(L * DM + 255) / 256, 256>>>(fe);       // 2
    k_cvt_w<<<(DI * DM + 255) / 256, 256>>>(inw);      // 3

    k_gemm1_wmma<<<dim3(DI / 128, L / 128), 256, G1_SMEM>>>();   // 4 <- ncu capture slot

    k_conv<<<((L / 4) * (DI / 4) + 255) / 256, 256>>>(convw, convb);

    k_gemm2<<<dim3(KS2, L / 64), 256>>>(xpw);
    k_xdblred<<<(L * 64 + 255) / 256, 256>>>();
    k_gemm3<<<dim3(DI / 128, L / 128), 256>>>(dtw, dtb);

    k_chunksuf<<<(DI + 255) / 256, 256>>>();
    k_scan<<<dim3(DI / 128, NCHUNK), 128>>>();
    k_hred<<<(DI * DS + 255) / 256, 256>>>();

    k_zc<<<((DI + DS) * 32 + 255) / 256, 256>>>(fe, inw, xpw);
    k_y<<<(DI + 255) / 256, 256>>>(Dp);
    k_out1<<<DM, 256>>>(outw);
    k_out2<<<1, 768>>>(out);
}